// round 10
// baseline (speedup 1.0000x reference)
#include <cuda_runtime.h>
#include <cuda_bf16.h>
#include <cstdint>

#define TOKENS 8192
#define DM 1024
#define DFF 4096
#define NHEAD 16
#define DHEAD 64
#define HALFBUF ((size_t)TOKENS * DM)  // elements in one bf16 half-buffer

// ---------------- scratch (device globals; no runtime alloc allowed) ----------------
__device__ __nv_bfloat16 g_Xh[TOKENS * DM], g_Xl[TOKENS * DM];
__device__ __nv_bfloat16 g_Yh[TOKENS * DM], g_Yl[TOKENS * DM];
__device__ __nv_bfloat16 g_Ch[TOKENS * DM], g_Cl[TOKENS * DM];
__device__ __nv_bfloat16 g_Hh[(size_t)TOKENS * DFF], g_Hl[(size_t)TOKENS * DFF];
__device__ float g_Q[TOKENS * DM];   // holds Qh|Ql bf16 halves
__device__ float g_K[TOKENS * DM];   // holds Kh|Kl
__device__ float g_V[TOKENS * DM];   // holds Vth|Vtl (V transposed [BH,64,S])
__device__ float g_S2[TOKENS * DM];
__device__ float g_bqkv[3 * DM];
__device__ __nv_bfloat16 g_Wqkvh[3 * DM * DM], g_Wqkvl[3 * DM * DM];
__device__ __nv_bfloat16 g_Woh[DM * DM], g_Wol[DM * DM];
__device__ __nv_bfloat16 g_W1h[(size_t)DM * DFF], g_W1l[(size_t)DM * DFF];
__device__ __nv_bfloat16 g_W2h[(size_t)DM * DFF], g_W2l[(size_t)DM * DFF];

// ---------------- PTX helpers ----------------
__device__ __forceinline__ uint32_t smem_u32(const void* p) {
    uint32_t a;
    asm("{ .reg .u64 t; cvta.to.shared.u64 t, %1; cvt.u32.u64 %0, t; }" : "=r"(a) : "l"(p));
    return a;
}
__device__ __forceinline__ void cpa16(uint32_t s, const void* g) {
    asm volatile("cp.async.cg.shared.global [%0], [%1], 16;" :: "r"(s), "l"(g));
}
__device__ __forceinline__ void ldm4(uint32_t* r, uint32_t addr) {
    asm volatile("ldmatrix.sync.aligned.m8n8.x4.shared.b16 {%0,%1,%2,%3}, [%4];"
                 : "=r"(r[0]), "=r"(r[1]), "=r"(r[2]), "=r"(r[3])
                 : "r"(addr));
}
__device__ __forceinline__ void mma_bf16(float* c, const uint32_t* a, const uint32_t* b) {
    asm volatile(
        "mma.sync.aligned.m16n8k16.row.col.f32.bf16.bf16.f32 "
        "{%0,%1,%2,%3}, {%4,%5,%6,%7}, {%8,%9}, {%0,%1,%2,%3};"
        : "+f"(c[0]), "+f"(c[1]), "+f"(c[2]), "+f"(c[3])
        : "r"(a[0]), "r"(a[1]), "r"(a[2]), "r"(a[3]), "r"(b[0]), "r"(b[1]));
}
__device__ __forceinline__ void split_bf16(float v, __nv_bfloat16& h, __nv_bfloat16& l) {
    h = __float2bfloat16(v);
    l = __float2bfloat16(v - __bfloat162float(h));
}
__device__ __forceinline__ uint32_t pack_bf2(__nv_bfloat16 a, __nv_bfloat16 b) {
    __nv_bfloat162 t;
    t.x = a;
    t.y = b;
    return *(uint32_t*)&t;
}

// ------- fused QKV weight transpose+split + bias concat -------
__global__ void __launch_bounds__(256) wconv3_k(const float* __restrict__ Wq,
                                                const float* __restrict__ Wk,
                                                const float* __restrict__ Wv,
                                                const float* __restrict__ bq,
                                                const float* __restrict__ bk,
                                                const float* __restrict__ bv,
                                                __nv_bfloat16* __restrict__ Th,
                                                __nv_bfloat16* __restrict__ Tl,
                                                float* __restrict__ bqkv) {
    const int z = blockIdx.z;
    const float* W = (z == 0) ? Wq : (z == 1) ? Wk : Wv;
    const float* bi = (z == 0) ? bq : (z == 1) ? bk : bv;
    __nv_bfloat16* Tz = Th + (size_t)z * DM * DM;
    __nv_bfloat16* Tzl = Tl + (size_t)z * DM * DM;

    __shared__ float t[32][33];
    const int bx = blockIdx.x * 32;
    const int by = blockIdx.y * 32;
    const int x = threadIdx.x;
    const int y0 = threadIdx.y;
#pragma unroll
    for (int dy = 0; dy < 32; dy += 8)
        t[y0 + dy][x] = W[(size_t)(by + y0 + dy) * DM + bx + x];
    __syncthreads();
#pragma unroll
    for (int dy = 0; dy < 32; dy += 8) {
        const float v = t[x][y0 + dy];
        __nv_bfloat16 h, l;
        split_bf16(v, h, l);
        const size_t o = (size_t)(bx + y0 + dy) * DM + by + x;
        Tz[o] = h;
        Tzl[o] = l;
    }
    if (blockIdx.y == 0 && y0 == 0) bqkv[z * DM + bx + x] = bi[bx + x];
}

// ---------------- generic weight transpose + split ----------------
__global__ void __launch_bounds__(256) wconv_k(const float* __restrict__ W,
                                               __nv_bfloat16* __restrict__ Th,
                                               __nv_bfloat16* __restrict__ Tl,
                                               int K, int N) {
    __shared__ float t[32][33];
    const int bx = blockIdx.x * 32;
    const int by = blockIdx.y * 32;
    const int x = threadIdx.x;
    const int y0 = threadIdx.y;
#pragma unroll
    for (int dy = 0; dy < 32; dy += 8)
        t[y0 + dy][x] = W[(size_t)(by + y0 + dy) * N + bx + x];
    __syncthreads();
#pragma unroll
    for (int dy = 0; dy < 32; dy += 8) {
        const float v = t[x][y0 + dy];
        __nv_bfloat16 h, l;
        split_bf16(v, h, l);
        const size_t o = (size_t)(bx + y0 + dy) * K + by + x;
        Th[o] = h;
        Tl[o] = l;
    }
}

// ---------------- LayerNorm: writes bf16 hi/lo ----------------
__global__ void __launch_bounds__(256) ln_k(const float* __restrict__ x,
                                            const float* __restrict__ g,
                                            const float* __restrict__ be,
                                            __nv_bfloat16* __restrict__ yh,
                                            __nv_bfloat16* __restrict__ yl) {
    const int row = blockIdx.x;
    const int t = threadIdx.x;
    const size_t base = (size_t)row * DM;
    const float4 v = *(const float4*)(x + base + t * 4);
    float s = v.x + v.y + v.z + v.w;
    float q = v.x * v.x + v.y * v.y + v.z * v.z + v.w * v.w;
#pragma unroll
    for (int off = 16; off; off >>= 1) {
        s += __shfl_xor_sync(0xffffffffu, s, off);
        q += __shfl_xor_sync(0xffffffffu, q, off);
    }
    __shared__ float rs[8], rq[8];
    if ((t & 31) == 0) { rs[t >> 5] = s; rq[t >> 5] = q; }
    __syncthreads();
    s = 0.f; q = 0.f;
#pragma unroll
    for (int i = 0; i < 8; ++i) { s += rs[i]; q += rq[i]; }
    const float mu = s * (1.0f / DM);
    const float var = q * (1.0f / DM) - mu * mu;
    const float r = rsqrtf(var + 1e-5f);
    const float4 gv = *(const float4*)(g + t * 4);
    const float4 bv = *(const float4*)(be + t * 4);
    float yv[4];
    yv[0] = (v.x - mu) * r * gv.x + bv.x;
    yv[1] = (v.y - mu) * r * gv.y + bv.y;
    yv[2] = (v.z - mu) * r * gv.z + bv.z;
    yv[3] = (v.w - mu) * r * gv.w + bv.w;
    __nv_bfloat16 h[4], l[4];
#pragma unroll
    for (int i = 0; i < 4; ++i) split_bf16(yv[i], h[i], l[i]);
    __nv_bfloat162 h01, h23, l01, l23;
    h01.x = h[0]; h01.y = h[1]; h23.x = h[2]; h23.y = h[3];
    l01.x = l[0]; l01.y = l[1]; l23.x = l[2]; l23.y = l[3];
    *(__nv_bfloat162*)(yh + base + t * 4) = h01;
    *(__nv_bfloat162*)(yh + base + t * 4 + 2) = h23;
    *(__nv_bfloat162*)(yl + base + t * 4) = l01;
    *(__nv_bfloat162*)(yl + base + t * 4 + 2) = l23;
}

// ---------------- split-bf16 HMMA GEMM, 512 threads, tile 128x256 ----------------
// Term-major MMA order: all Ah*Bh, then Ah*Bl, then Al*Bh — no back-to-back
// accumulator dependency chains (asm volatile preserves program order).
#define HBK 32
#define SROW 80
#define A_BYTES 10240
#define B_BYTES 20480
#define STAGE_B (2 * A_BYTES + 2 * B_BYTES)
#define NST 3
#define SMEM_G (NST * STAGE_B)

template <int EPI>
__global__ void __launch_bounds__(512, 1)
hgemm(const __nv_bfloat16* __restrict__ Ah, const __nv_bfloat16* __restrict__ Al,
      const __nv_bfloat16* __restrict__ Bh, const __nv_bfloat16* __restrict__ Bl,
      const float* __restrict__ bias, const float* __restrict__ res,
      float* __restrict__ Cf, float* __restrict__ Cf2, float* __restrict__ Cf3,
      __nv_bfloat16* __restrict__ Ch, __nv_bfloat16* __restrict__ Cl,
      int M, int N, int K) {
    extern __shared__ char sm[];
    const uint32_t smb = smem_u32(sm);
    const int tid = threadIdx.x;
    const int wid = tid >> 5;
    const int lane = tid & 31;
    const int wm = wid & 1;
    const int wn = wid >> 1;
    const int bm = blockIdx.y * 128;
    const int bn = blockIdx.x * 256;
    const int nch = K / HBK;

    auto load_stage = [&](int chunk, int s) {
        const int k0 = chunk * HBK;
        const uint32_t base = smb + s * STAGE_B;
#pragma unroll
        for (int it = 0; it < 3; ++it) {
            const int idx = tid + (it << 9);
            const int r = idx >> 2, c4 = idx & 3;
            if (r < 128) {
                const uint32_t dst = base + r * SROW + c4 * 16;
                const size_t go = ((size_t)(bm + r) * K + k0 + c4 * 8) * 2;
                cpa16(dst, (const char*)Ah + go);
                cpa16(dst + A_BYTES, (const char*)Al + go);
            } else {
                const int rb = r - 128;
                const uint32_t dst = base + 2 * A_BYTES + rb * SROW + c4 * 16;
                const size_t go = ((size_t)(bn + rb) * K + k0 + c4 * 8) * 2;
                cpa16(dst, (const char*)Bh + go);
                cpa16(dst + B_BYTES, (const char*)Bl + go);
            }
        }
        asm volatile("cp.async.commit_group;");
    };

    float acc[4][4][4];
#pragma unroll
    for (int a = 0; a < 4; ++a)
#pragma unroll
        for (int b = 0; b < 4; ++b)
#pragma unroll
            for (int c = 0; c < 4; ++c) acc[a][b][c] = 0.f;

#pragma unroll
    for (int s = 0; s < NST - 1; ++s)
        if (s < nch) load_stage(s, s);

    const uint32_t a_row = (lane & 15);
    const uint32_t a_koff = ((lane >> 4) << 3);
    const uint32_t b_row = (lane & 7) + (((lane >> 4) & 1) << 3);
    const uint32_t b_koff = (((lane >> 3) & 1) << 3);

    for (int i = 0; i < nch; ++i) {
        if (i + NST - 1 <= nch) {
            asm volatile("cp.async.wait_group %0;" :: "n"(NST - 2));
        } else {
            asm volatile("cp.async.wait_group 0;");
        }
        __syncthreads();
        if (i + NST - 1 < nch) load_stage(i + NST - 1, (i + NST - 1) % NST);

        const uint32_t sb = smb + (i % NST) * STAGE_B;
#pragma unroll
        for (int ks = 0; ks < 2; ++ks) {
            const int k0 = ks * 16;
            uint32_t afh[4][4], afl[4][4];
#pragma unroll
            for (int mi = 0; mi < 4; ++mi) {
                const uint32_t addr =
                    sb + (wm * 64 + mi * 16 + a_row) * SROW + (k0 + a_koff) * 2;
                ldm4(afh[mi], addr);
                ldm4(afl[mi], addr + A_BYTES);
            }
            uint32_t bfh[2][4], bfl[2][4];
#pragma unroll
            for (int g = 0; g < 2; ++g) {
                const uint32_t addr =
                    sb + 2 * A_BYTES + (wn * 32 + g * 16 + b_row) * SROW + (k0 + b_koff) * 2;
                ldm4(bfh[g], addr);
                ldm4(bfl[g], addr + B_BYTES);
            }
            // term-major: 16 independent MMAs per pass, chains 16 apart
#pragma unroll
            for (int mi = 0; mi < 4; ++mi)
#pragma unroll
                for (int ni = 0; ni < 4; ++ni)
                    mma_bf16(acc[mi][ni], afh[mi], &bfh[ni >> 1][(ni & 1) * 2]);
#pragma unroll
            for (int mi = 0; mi < 4; ++mi)
#pragma unroll
                for (int ni = 0; ni < 4; ++ni)
                    mma_bf16(acc[mi][ni], afh[mi], &bfl[ni >> 1][(ni & 1) * 2]);
#pragma unroll
            for (int mi = 0; mi < 4; ++mi)
#pragma unroll
                for (int ni = 0; ni < 4; ++ni)
                    mma_bf16(acc[mi][ni], afl[mi], &bfh[ni >> 1][(ni & 1) * 2]);
        }
    }

    // epilogue
    const int er = lane >> 2;
    const int ec = (lane & 3) * 2;
#pragma unroll
    for (int mi = 0; mi < 4; ++mi)
#pragma unroll
        for (int ni = 0; ni < 4; ++ni) {
#pragma unroll
            for (int half = 0; half < 2; ++half) {
                const int row = bm + wm * 64 + mi * 16 + er + half * 8;
                const int col = bn + wn * 32 + ni * 8 + ec;
                float v0 = acc[mi][ni][half * 2 + 0] + bias[col];
                float v1 = acc[mi][ni][half * 2 + 1] + bias[col + 1];
                if (EPI == 1) {
                    v0 = fmaxf(v0, 0.f);
                    v1 = fmaxf(v1, 0.f);
                    __nv_bfloat16 h0, l0, h1, l1;
                    split_bf16(v0, h0, l0);
                    split_bf16(v1, h1, l1);
                    const size_t o = (size_t)row * N + col;
                    *(__nv_bfloat162*)(Ch + o) = __nv_bfloat162{h0, h1};
                    *(__nv_bfloat162*)(Cl + o) = __nv_bfloat162{l0, l1};
                } else if (EPI == 2) {
                    const size_t o = (size_t)row * N + col;
                    const float2 rv = *(const float2*)(res + o);
                    float2 ov;
                    ov.x = v0 + rv.x;
                    ov.y = v1 + rv.y;
                    *(float2*)(Cf + o) = ov;
                } else {  // EPI == 3: QKV scatter; Q scaled; V transposed
                    const int t = col >> 10;
                    const int cc = col & 1023;
                    const int b = row >> 10, s = row & 1023;
                    const int h = cc >> 6, d = cc & 63;
                    if (t == 0) { v0 *= 0.125f; v1 *= 0.125f; }
                    __nv_bfloat16 h0, l0, h1, l1;
                    split_bf16(v0, h0, l0);
                    split_bf16(v1, h1, l1);
                    if (t < 2) {
                        __nv_bfloat16* Dh = (__nv_bfloat16*)(t == 0 ? Cf : Cf2);
                        __nv_bfloat16* Dl = Dh + HALFBUF;
                        const size_t o = ((size_t)(b * NHEAD + h) * 1024 + s) * DHEAD + d;
                        *(__nv_bfloat162*)(Dh + o) = __nv_bfloat162{h0, h1};
                        *(__nv_bfloat162*)(Dl + o) = __nv_bfloat162{l0, l1};
                    } else {
                        __nv_bfloat16* Dh = (__nv_bfloat16*)Cf3;
                        __nv_bfloat16* Dl = Dh + HALFBUF;
                        const size_t o0 = ((size_t)(b * NHEAD + h) * DHEAD + d) * 1024 + s;
                        Dh[o0] = h0;
                        Dl[o0] = l0;
                        Dh[o0 + 1024] = h1;
                        Dl[o0 + 1024] = l1;
                    }
                }
            }
        }
}

// ---------------- split-bf16 HMMA flash attention (term-major MMA order) ----------------
#define AST 144
#define AQ_B 18432
#define AKV_T 9216
#define AKV_STAGE 36864
#define ATT_SMEM (2 * AQ_B + 3 * AKV_STAGE)  // 147456

__global__ void __launch_bounds__(256, 1)
attn_k(const __nv_bfloat16* __restrict__ Qhp, const __nv_bfloat16* __restrict__ Khp,
       const __nv_bfloat16* __restrict__ Vhp,
       __nv_bfloat16* __restrict__ CTXh, __nv_bfloat16* __restrict__ CTXl) {
    const __nv_bfloat16* Qlp = Qhp + HALFBUF;
    const __nv_bfloat16* Klp = Khp + HALFBUF;
    const __nv_bfloat16* Vlp = Vhp + HALFBUF;

    extern __shared__ char sm[];
    const uint32_t smb = smem_u32(sm);
    const uint32_t QS = smb;
    const uint32_t KST0 = smb + 2 * AQ_B;

    const int tid = threadIdx.x;
    const int wid = tid >> 5;
    const int lane = tid & 31;
    const int bh = blockIdx.y;
    const int q0 = blockIdx.x << 7;

    // Q tile load (joins group of kv tile 0)
    {
#pragma unroll
        for (int it = 0; it < 8; ++it) {
            const int idx = tid + (it << 8);
            const int hl = idx >> 10;
            const int rem = idx & 1023;
            const int r = rem >> 3;
            const int c = rem & 7;
            const uint32_t dst = QS + hl * AQ_B + r * AST + c * 16;
            const char* src = (const char*)(hl ? Qlp : Qhp) +
                              (size_t)((bh << 10) + q0 + r) * 128 + c * 16;
            cpa16(dst, src);
        }
    }

    auto load_kv = [&](int kt, int s) {
        const uint32_t base = KST0 + s * AKV_STAGE;
#pragma unroll
        for (int it = 0; it < 8; ++it) {
            const int idx = tid + (it << 8);
            const int tensor = idx >> 10;
            const int rem = idx & 1023;
            const int r = rem >> 4;
            const int c = (rem >> 1) & 7;
            const int hl = rem & 1;
            if (tensor == 0) {
                const uint32_t dst = base + hl * AKV_T + r * AST + c * 16;
                const char* src = (const char*)(hl ? Klp : Khp) +
                                  (size_t)((bh << 10) + (kt << 6) + r) * 128 + c * 16;
                cpa16(dst, src);
            } else {
                const uint32_t dst = base + 2 * AKV_T + hl * AKV_T + r * AST + c * 16;
                const char* src = (const char*)(hl ? Vlp : Vhp) +
                                  (((size_t)(bh * 64 + r) << 10) + (kt << 6)) * 2 + c * 16;
                cpa16(dst, src);
            }
        }
        asm volatile("cp.async.commit_group;");
    };

    load_kv(0, 0);
    load_kv(1, 1);

    float m0 = -1e30f, m1 = -1e30f, l0 = 0.f, l1 = 0.f;
    float oacc[8][4];
#pragma unroll
    for (int i = 0; i < 8; ++i)
#pragma unroll
        for (int j = 0; j < 4; ++j) oacc[i][j] = 0.f;

    const uint32_t a_row = (lane & 15);
    const uint32_t a_koff = ((lane >> 4) << 3);
    const uint32_t b_row = (lane & 7) + (((lane >> 4) & 1) << 3);
    const uint32_t b_koff = (((lane >> 3) & 1) << 3);

    for (int kt = 0; kt < 16; ++kt) {
        if (kt + 2 <= 16) {
            asm volatile("cp.async.wait_group 1;");
        } else {
            asm volatile("cp.async.wait_group 0;");
        }
        __syncthreads();
        if (kt + 2 < 16) load_kv(kt + 2, (kt + 2) % 3);

        const uint32_t st = KST0 + (kt % 3) * AKV_STAGE;

        // ---- S = Q K^T (term-major) ----
        float sacc[8][4];
#pragma unroll
        for (int i = 0; i < 8; ++i)
#pragma unroll
            for (int j = 0; j < 4; ++j) sacc[i][j] = 0.f;
#pragma unroll
        for (int kc = 0; kc < 4; ++kc) {
            uint32_t afh[4], afl[4];
            const uint32_t aaddr = QS + (wid * 16 + a_row) * AST + (kc * 16 + a_koff) * 2;
            ldm4(afh, aaddr);
            ldm4(afl, aaddr + AQ_B);
            uint32_t bkh[4][4], bkl[4][4];
#pragma unroll
            for (int g = 0; g < 4; ++g) {
                const uint32_t baddr = st + (g * 16 + b_row) * AST + (kc * 16 + b_koff) * 2;
                ldm4(bkh[g], baddr);
                ldm4(bkl[g], baddr + AKV_T);
            }
#pragma unroll
            for (int ni = 0; ni < 8; ++ni)
                mma_bf16(sacc[ni], afh, &bkh[ni >> 1][(ni & 1) * 2]);
#pragma unroll
            for (int ni = 0; ni < 8; ++ni)
                mma_bf16(sacc[ni], afh, &bkl[ni >> 1][(ni & 1) * 2]);
#pragma unroll
            for (int ni = 0; ni < 8; ++ni)
                mma_bf16(sacc[ni], afl, &bkh[ni >> 1][(ni & 1) * 2]);
        }

        // ---- online softmax ----
        float rmax0 = -1e30f, rmax1 = -1e30f;
#pragma unroll
        for (int ni = 0; ni < 8; ++ni) {
            rmax0 = fmaxf(rmax0, fmaxf(sacc[ni][0], sacc[ni][1]));
            rmax1 = fmaxf(rmax1, fmaxf(sacc[ni][2], sacc[ni][3]));
        }
        rmax0 = fmaxf(rmax0, __shfl_xor_sync(0xffffffffu, rmax0, 1));
        rmax0 = fmaxf(rmax0, __shfl_xor_sync(0xffffffffu, rmax0, 2));
        rmax1 = fmaxf(rmax1, __shfl_xor_sync(0xffffffffu, rmax1, 1));
        rmax1 = fmaxf(rmax1, __shfl_xor_sync(0xffffffffu, rmax1, 2));
        const float mn0 = fmaxf(m0, rmax0);
        const float mn1 = fmaxf(m1, rmax1);
        const float cor0 = __expf(m0 - mn0);
        const float cor1 = __expf(m1 - mn1);
        float rs0 = 0.f, rs1 = 0.f;
#pragma unroll
        for (int ni = 0; ni < 8; ++ni) {
            sacc[ni][0] = __expf(sacc[ni][0] - mn0);
            sacc[ni][1] = __expf(sacc[ni][1] - mn0);
            sacc[ni][2] = __expf(sacc[ni][2] - mn1);
            sacc[ni][3] = __expf(sacc[ni][3] - mn1);
            rs0 += sacc[ni][0] + sacc[ni][1];
            rs1 += sacc[ni][2] + sacc[ni][3];
        }
        rs0 += __shfl_xor_sync(0xffffffffu, rs0, 1);
        rs0 += __shfl_xor_sync(0xffffffffu, rs0, 2);
        rs1 += __shfl_xor_sync(0xffffffffu, rs1, 1);
        rs1 += __shfl_xor_sync(0xffffffffu, rs1, 2);
        l0 = l0 * cor0 + rs0;
        l1 = l1 * cor1 + rs1;
        m0 = mn0;
        m1 = mn1;
#pragma unroll
        for (int ni = 0; ni < 8; ++ni) {
            oacc[ni][0] *= cor0;
            oacc[ni][1] *= cor0;
            oacc[ni][2] *= cor1;
            oacc[ni][3] *= cor1;
        }

        // ---- O += P V (term-major) ----
#pragma unroll
        for (int j = 0; j < 4; ++j) {
            uint32_t pah[4], pal[4];
#pragma unroll
            for (int tt = 0; tt < 2; ++tt) {
                const float* sc = sacc[2 * j + tt];
#pragma unroll
                for (int q = 0; q < 2; ++q) {
                    const float v0 = sc[2 * q], v1 = sc[2 * q + 1];
                    __nv_bfloat16 h0, e0, h1, e1;
                    split_bf16(v0, h0, e0);
                    split_bf16(v1, h1, e1);
                    pah[2 * tt + q] = pack_bf2(h0, h1);
                    pal[2 * tt + q] = pack_bf2(e0, e1);
                }
            }
            uint32_t bvh[4][4], bvl[4][4];
#pragma unroll
            for (int g = 0; g < 4; ++g) {
                const uint32_t baddr =
                    st + 2 * AKV_T + (g * 16 + b_row) * AST + (j * 16 + b_koff) * 2;
                ldm4(bvh[g], baddr);
                ldm4(bvl[g], baddr + AKV_T);
            }
#pragma unroll
            for (int ni = 0; ni < 8; ++ni)
                mma_bf16(oacc[ni], pah, &bvh[ni >> 1][(ni & 1) * 2]);
#pragma unroll
            for (int ni = 0; ni < 8; ++ni)
                mma_bf16(oacc[ni], pah, &bvl[ni >> 1][(ni & 1) * 2]);
#pragma unroll
            for (int ni = 0; ni < 8; ++ni)
                mma_bf16(oacc[ni], pal, &bvh[ni >> 1][(ni & 1) * 2]);
        }
    }

    // ---- epilogue ----
    const float inv0 = 1.0f / l0;
    const float inv1 = 1.0f / l1;
    const int b = bh >> 4, h = bh & 15;
    const int row0 = q0 + wid * 16 + (lane >> 2);
    const int ec = (lane & 3) * 2;
#pragma unroll
    for (int ni = 0; ni < 8; ++ni) {
        const int col = h * 64 + ni * 8 + ec;
        {
            const float v0 = oacc[ni][0] * inv0, v1 = oacc[ni][1] * inv0;
            __nv_bfloat16 h0, e0, h1, e1;
            split_bf16(v0, h0, e0);
            split_bf16(v1, h1, e1);
            const size_t o = ((size_t)(b * 1024 + row0) * DM) + col;
            *(__nv_bfloat162*)(CTXh + o) = __nv_bfloat162{h0, h1};
            *(__nv_bfloat162*)(CTXl + o) = __nv_bfloat162{e0, e1};
        }
        {
            const float v0 = oacc[ni][2] * inv1, v1 = oacc[ni][3] * inv1;
            __nv_bfloat16 h0, e0, h1, e1;
            split_bf16(v0, h0, e0);
            split_bf16(v1, h1, e1);
            const size_t o = ((size_t)(b * 1024 + row0 + 8) * DM) + col;
            *(__nv_bfloat162*)(CTXh + o) = __nv_bfloat162{h0, h1};
            *(__nv_bfloat162*)(CTXl + o) = __nv_bfloat162{e0, e1};
        }
    }
}

// ---------------- launch ----------------
extern "C" void kernel_launch(void* const* d_in, const int* in_sizes, int n_in,
                              void* d_out, int out_size) {
    const float* src = (const float*)d_in[0];
    const float* Wq = (const float*)d_in[1];
    const float* bq = (const float*)d_in[2];
    const float* Wk = (const float*)d_in[3];
    const float* bk = (const float*)d_in[4];
    const float* Wv = (const float*)d_in[5];
    const float* bv = (const float*)d_in[6];
    const float* Wo = (const float*)d_in[7];
    const float* bo = (const float*)d_in[8];
    const float* W1 = (const float*)d_in[9];
    const float* b1 = (const float*)d_in[10];
    const float* W2 = (const float*)d_in[11];
    const float* b2 = (const float*)d_in[12];
    const float* g1 = (const float*)d_in[13];
    const float* be1 = (const float*)d_in[14];
    const float* g2 = (const float*)d_in[15];
    const float* be2 = (const float*)d_in[16];
    float* out = (float*)d_out;

#define SYM(p, s) cudaGetSymbolAddress((void**)&p, s)
    __nv_bfloat16 *Xh, *Xl, *Yh, *Yl, *Chb, *Clb, *Hh, *Hl;
    __nv_bfloat16 *Wqkvh, *Wqkvl, *Woh, *Wol, *W1h, *W1l, *W2h, *W2l;
    float *Qb, *Kb, *Vb, *S2, *bqkv;
    SYM(Xh, g_Xh); SYM(Xl, g_Xl); SYM(Yh, g_Yh); SYM(Yl, g_Yl);
    SYM(Chb, g_Ch); SYM(Clb, g_Cl); SYM(Hh, g_Hh); SYM(Hl, g_Hl);
    SYM(Qb, g_Q); SYM(Kb, g_K); SYM(Vb, g_V); SYM(S2, g_S2); SYM(bqkv, g_bqkv);
    SYM(Wqkvh, g_Wqkvh); SYM(Wqkvl, g_Wqkvl);
    SYM(Woh, g_Woh); SYM(Wol, g_Wol);
    SYM(W1h, g_W1h); SYM(W1l, g_W1l); SYM(W2h, g_W2h); SYM(W2l, g_W2l);
#undef SYM

    cudaFuncSetAttribute(attn_k, cudaFuncAttributeMaxDynamicSharedMemorySize, ATT_SMEM);
    cudaFuncSetAttribute(hgemm<1>, cudaFuncAttributeMaxDynamicSharedMemorySize, SMEM_G);
    cudaFuncSetAttribute(hgemm<2>, cudaFuncAttributeMaxDynamicSharedMemorySize, SMEM_G);
    cudaFuncSetAttribute(hgemm<3>, cudaFuncAttributeMaxDynamicSharedMemorySize, SMEM_G);

    dim3 cb(32, 8);
    // kernel 1: fused QKV weight conv + bias concat
    wconv3_k<<<dim3(DM / 32, DM / 32, 3), cb>>>(Wq, Wk, Wv, bq, bk, bv, Wqkvh, Wqkvl, bqkv);
    // kernel 2: LN1
    ln_k<<<TOKENS, 256>>>(src, g1, be1, Xh, Xl);
    // kernel 3: Wo conv
    wconv_k<<<dim3(DM / 32, DM / 32), cb>>>(Wo, Woh, Wol, DM, DM);

    // kernel 4: fused QKV GEMM (N=3072) — profiled
    hgemm<3><<<dim3(12, 64), 512, SMEM_G>>>(
        Xh, Xl, Wqkvh, Wqkvl, bqkv, nullptr, Qb, Kb, Vb, nullptr, nullptr, TOKENS, 3 * DM, DM);

    // kernel 5: HMMA flash attention -> CTX bf16 pair
    attn_k<<<dim3(8, 128), 256, ATT_SMEM>>>(
        (const __nv_bfloat16*)Qb, (const __nv_bfloat16*)Kb, (const __nv_bfloat16*)Vb, Chb, Clb);

    // Wo + residual(src) -> S2 fp32
    hgemm<2><<<dim3(4, 64), 512, SMEM_G>>>(
        Chb, Clb, Woh, Wol, bo, src, S2, nullptr, nullptr, nullptr, nullptr, TOKENS, DM, DM);

    // LN2 -> Y bf16 pair
    ln_k<<<TOKENS, 256>>>(S2, g2, be2, Yh, Yl);

    // W1 + relu -> H bf16 pair
    wconv_k<<<dim3(DFF / 32, DM / 32), cb>>>(W1, W1h, W1l, DM, DFF);
    hgemm<1><<<dim3(16, 64), 512, SMEM_G>>>(
        Yh, Yl, W1h, W1l, b1, nullptr, nullptr, nullptr, nullptr, Hh, Hl, TOKENS, DFF, DM);

    // W2 + residual(S2) -> out fp32
    wconv_k<<<dim3(DM / 32, DFF / 32), cb>>>(W2, W2h, W2l, DFF, DM);
    hgemm<2><<<dim3(4, 64), 512, SMEM_G>>>(
        Hh, Hl, W2h, W2l, b2, S2, out, nullptr, nullptr, nullptr, nullptr, TOKENS, DM, DFF);
}

// round 13
// speedup vs baseline: 1.2237x; 1.2237x over previous
#include <cuda_runtime.h>
#include <cuda_bf16.h>
#include <cuda_fp16.h>
#include <cstdint>

#define TOKENS 8192
#define DM 1024
#define DFF 4096
#define NHEAD 16
#define DHEAD 64
#define HALFBUF ((size_t)TOKENS * DM)  // elements in one bf16 half-buffer

// ---------------- scratch (device globals; no runtime alloc allowed) ----------------
__device__ __nv_bfloat16 g_Xh[TOKENS * DM], g_Xl[TOKENS * DM];   // LN1 out (bf16 pair)
__device__ __half g_Cx[TOKENS * DM];                              // ctx (fp16 single)
__device__ __half g_Y2[TOKENS * DM];                              // LN2 out (fp16 single)
__device__ __half g_Hx[(size_t)TOKENS * DFF];                     // ffn hidden (fp16 single)
__device__ float g_Q[TOKENS * DM];   // Qh|Ql bf16 halves
__device__ float g_K[TOKENS * DM];   // Kh|Kl
__device__ float g_V[TOKENS * DM];   // Vth|Vtl (V transposed [BH,64,S])
__device__ float g_S2[TOKENS * DM];
__device__ float g_bqkv[3 * DM];
__device__ __nv_bfloat16 g_Wqkvh[3 * DM * DM], g_Wqkvl[3 * DM * DM];  // bf16 pair
__device__ __half g_Woh[DM * DM], g_Wol[DM * DM];                     // fp16 pair
__device__ __half g_W1h[(size_t)DM * DFF], g_W1l[(size_t)DM * DFF];
__device__ __half g_W2h[(size_t)DM * DFF], g_W2l[(size_t)DM * DFF];

// ---------------- PTX helpers ----------------
__device__ __forceinline__ uint32_t smem_u32(const void* p) {
    uint32_t a;
    asm("{ .reg .u64 t; cvta.to.shared.u64 t, %1; cvt.u32.u64 %0, t; }" : "=r"(a) : "l"(p));
    return a;
}
__device__ __forceinline__ void cpa16(uint32_t s, const void* g) {
    asm volatile("cp.async.cg.shared.global [%0], [%1], 16;" :: "r"(s), "l"(g));
}
__device__ __forceinline__ void ldm4(uint32_t* r, uint32_t addr) {
    asm volatile("ldmatrix.sync.aligned.m8n8.x4.shared.b16 {%0,%1,%2,%3}, [%4];"
                 : "=r"(r[0]), "=r"(r[1]), "=r"(r[2]), "=r"(r[3])
                 : "r"(addr));
}
__device__ __forceinline__ void mma_bf16(float* c, const uint32_t* a, const uint32_t* b) {
    asm volatile(
        "mma.sync.aligned.m16n8k16.row.col.f32.bf16.bf16.f32 "
        "{%0,%1,%2,%3}, {%4,%5,%6,%7}, {%8,%9}, {%0,%1,%2,%3};"
        : "+f"(c[0]), "+f"(c[1]), "+f"(c[2]), "+f"(c[3])
        : "r"(a[0]), "r"(a[1]), "r"(a[2]), "r"(a[3]), "r"(b[0]), "r"(b[1]));
}
__device__ __forceinline__ void mma_fp16(float* c, const uint32_t* a, const uint32_t* b) {
    asm volatile(
        "mma.sync.aligned.m16n8k16.row.col.f32.f16.f16.f32 "
        "{%0,%1,%2,%3}, {%4,%5,%6,%7}, {%8,%9}, {%0,%1,%2,%3};"
        : "+f"(c[0]), "+f"(c[1]), "+f"(c[2]), "+f"(c[3])
        : "r"(a[0]), "r"(a[1]), "r"(a[2]), "r"(a[3]), "r"(b[0]), "r"(b[1]));
}
__device__ __forceinline__ void split_bf16(float v, __nv_bfloat16& h, __nv_bfloat16& l) {
    h = __float2bfloat16(v);
    l = __float2bfloat16(v - __bfloat162float(h));
}
__device__ __forceinline__ void split_h(float v, __half& h, __half& l) {
    h = __float2half_rn(v);
    l = __float2half_rn(v - __half2float(h));
}
__device__ __forceinline__ uint32_t pack_bf2(__nv_bfloat16 a, __nv_bfloat16 b) {
    __nv_bfloat162 t;
    t.x = a;
    t.y = b;
    return *(uint32_t*)&t;
}

// ------- fused QKV weight transpose+split (bf16 pair) + bias concat -------
__global__ void __launch_bounds__(256) wconv3_k(const float* __restrict__ Wq,
                                                const float* __restrict__ Wk,
                                                const float* __restrict__ Wv,
                                                const float* __restrict__ bq,
                                                const float* __restrict__ bk,
                                                const float* __restrict__ bv,
                                                __nv_bfloat16* __restrict__ Th,
                                                __nv_bfloat16* __restrict__ Tl,
                                                float* __restrict__ bqkv) {
    const int z = blockIdx.z;
    const float* W = (z == 0) ? Wq : (z == 1) ? Wk : Wv;
    const float* bi = (z == 0) ? bq : (z == 1) ? bk : bv;
    __nv_bfloat16* Tz = Th + (size_t)z * DM * DM;
    __nv_bfloat16* Tzl = Tl + (size_t)z * DM * DM;

    __shared__ float t[32][33];
    const int bx = blockIdx.x * 32;
    const int by = blockIdx.y * 32;
    const int x = threadIdx.x;
    const int y0 = threadIdx.y;
#pragma unroll
    for (int dy = 0; dy < 32; dy += 8)
        t[y0 + dy][x] = W[(size_t)(by + y0 + dy) * DM + bx + x];
    __syncthreads();
#pragma unroll
    for (int dy = 0; dy < 32; dy += 8) {
        const float v = t[x][y0 + dy];
        __nv_bfloat16 h, l;
        split_bf16(v, h, l);
        const size_t o = (size_t)(bx + y0 + dy) * DM + by + x;
        Tz[o] = h;
        Tzl[o] = l;
    }
    if (blockIdx.y == 0 && y0 == 0) bqkv[z * DM + bx + x] = bi[bx + x];
}

// ---------------- weight transpose + split to fp16 pair ----------------
__global__ void __launch_bounds__(256) wconvh_k(const float* __restrict__ W,
                                                __half* __restrict__ Th,
                                                __half* __restrict__ Tl,
                                                int K, int N) {
    __shared__ float t[32][33];
    const int bx = blockIdx.x * 32;
    const int by = blockIdx.y * 32;
    const int x = threadIdx.x;
    const int y0 = threadIdx.y;
#pragma unroll
    for (int dy = 0; dy < 32; dy += 8)
        t[y0 + dy][x] = W[(size_t)(by + y0 + dy) * N + bx + x];
    __syncthreads();
#pragma unroll
    for (int dy = 0; dy < 32; dy += 8) {
        const float v = t[x][y0 + dy];
        __half h, l;
        split_h(v, h, l);
        const size_t o = (size_t)(bx + y0 + dy) * K + by + x;
        Th[o] = h;
        Tl[o] = l;
    }
}

// ---------------- LayerNorm -> bf16 pair (feeds 3-term QKV GEMM) ----------------
__global__ void __launch_bounds__(256) ln_k(const float* __restrict__ x,
                                            const float* __restrict__ g,
                                            const float* __restrict__ be,
                                            __nv_bfloat16* __restrict__ yh,
                                            __nv_bfloat16* __restrict__ yl) {
    const int row = blockIdx.x;
    const int t = threadIdx.x;
    const size_t base = (size_t)row * DM;
    const float4 v = *(const float4*)(x + base + t * 4);
    float s = v.x + v.y + v.z + v.w;
    float q = v.x * v.x + v.y * v.y + v.z * v.z + v.w * v.w;
#pragma unroll
    for (int off = 16; off; off >>= 1) {
        s += __shfl_xor_sync(0xffffffffu, s, off);
        q += __shfl_xor_sync(0xffffffffu, q, off);
    }
    __shared__ float rs[8], rq[8];
    if ((t & 31) == 0) { rs[t >> 5] = s; rq[t >> 5] = q; }
    __syncthreads();
    s = 0.f; q = 0.f;
#pragma unroll
    for (int i = 0; i < 8; ++i) { s += rs[i]; q += rq[i]; }
    const float mu = s * (1.0f / DM);
    const float var = q * (1.0f / DM) - mu * mu;
    const float r = rsqrtf(var + 1e-5f);
    const float4 gv = *(const float4*)(g + t * 4);
    const float4 bv = *(const float4*)(be + t * 4);
    float yv[4];
    yv[0] = (v.x - mu) * r * gv.x + bv.x;
    yv[1] = (v.y - mu) * r * gv.y + bv.y;
    yv[2] = (v.z - mu) * r * gv.z + bv.z;
    yv[3] = (v.w - mu) * r * gv.w + bv.w;
    __nv_bfloat16 h[4], l[4];
#pragma unroll
    for (int i = 0; i < 4; ++i) split_bf16(yv[i], h[i], l[i]);
    __nv_bfloat162 h01, h23, l01, l23;
    h01.x = h[0]; h01.y = h[1]; h23.x = h[2]; h23.y = h[3];
    l01.x = l[0]; l01.y = l[1]; l23.x = l[2]; l23.y = l[3];
    *(__nv_bfloat162*)(yh + base + t * 4) = h01;
    *(__nv_bfloat162*)(yh + base + t * 4 + 2) = h23;
    *(__nv_bfloat162*)(yl + base + t * 4) = l01;
    *(__nv_bfloat162*)(yl + base + t * 4 + 2) = l23;
}

// ---------------- LayerNorm -> single fp16 (feeds 2-term FFN GEMM) ----------------
__global__ void __launch_bounds__(256) ln_h_k(const float* __restrict__ x,
                                              const float* __restrict__ g,
                                              const float* __restrict__ be,
                                              __half* __restrict__ y) {
    const int row = blockIdx.x;
    const int t = threadIdx.x;
    const size_t base = (size_t)row * DM;
    const float4 v = *(const float4*)(x + base + t * 4);
    float s = v.x + v.y + v.z + v.w;
    float q = v.x * v.x + v.y * v.y + v.z * v.z + v.w * v.w;
#pragma unroll
    for (int off = 16; off; off >>= 1) {
        s += __shfl_xor_sync(0xffffffffu, s, off);
        q += __shfl_xor_sync(0xffffffffu, q, off);
    }
    __shared__ float rs[8], rq[8];
    if ((t & 31) == 0) { rs[t >> 5] = s; rq[t >> 5] = q; }
    __syncthreads();
    s = 0.f; q = 0.f;
#pragma unroll
    for (int i = 0; i < 8; ++i) { s += rs[i]; q += rq[i]; }
    const float mu = s * (1.0f / DM);
    const float var = q * (1.0f / DM) - mu * mu;
    const float r = rsqrtf(var + 1e-5f);
    const float4 gv = *(const float4*)(g + t * 4);
    const float4 bv = *(const float4*)(be + t * 4);
    const float y0 = (v.x - mu) * r * gv.x + bv.x;
    const float y1 = (v.y - mu) * r * gv.y + bv.y;
    const float y2 = (v.z - mu) * r * gv.z + bv.z;
    const float y3 = (v.w - mu) * r * gv.w + bv.w;
    *(__half2*)(y + base + t * 4) = __floats2half2_rn(y0, y1);
    *(__half2*)(y + base + t * 4 + 2) = __floats2half2_rn(y2, y3);
}

// ---------------- split-bf16 3-term HMMA GEMM (QKV only), 512 thr, 128x256 -------
#define HBK 32
#define SROW 80
#define A_BYTES 10240
#define B_BYTES 20480
#define STAGE_B (2 * A_BYTES + 2 * B_BYTES)
#define NST 3
#define SMEM_G (NST * STAGE_B)

__global__ void __launch_bounds__(512, 1)
hgemm_qkv(const __nv_bfloat16* __restrict__ Ah, const __nv_bfloat16* __restrict__ Al,
          const __nv_bfloat16* __restrict__ Bh, const __nv_bfloat16* __restrict__ Bl,
          const float* __restrict__ bias,
          float* __restrict__ Cf, float* __restrict__ Cf2, float* __restrict__ Cf3,
          int M, int N, int K) {
    extern __shared__ char sm[];
    const uint32_t smb = smem_u32(sm);
    const int tid = threadIdx.x;
    const int wid = tid >> 5;
    const int lane = tid & 31;
    const int wm = wid & 1;
    const int wn = wid >> 1;
    const int bm = blockIdx.y * 128;
    const int bn = blockIdx.x * 256;
    const int nch = K / HBK;

    auto load_stage = [&](int chunk, int s) {
        const int k0 = chunk * HBK;
        const uint32_t base = smb + s * STAGE_B;
#pragma unroll
        for (int it = 0; it < 3; ++it) {
            const int idx = tid + (it << 9);
            const int r = idx >> 2, c4 = idx & 3;
            if (r < 128) {
                const uint32_t dst = base + r * SROW + c4 * 16;
                const size_t go = ((size_t)(bm + r) * K + k0 + c4 * 8) * 2;
                cpa16(dst, (const char*)Ah + go);
                cpa16(dst + A_BYTES, (const char*)Al + go);
            } else {
                const int rb = r - 128;
                const uint32_t dst = base + 2 * A_BYTES + rb * SROW + c4 * 16;
                const size_t go = ((size_t)(bn + rb) * K + k0 + c4 * 8) * 2;
                cpa16(dst, (const char*)Bh + go);
                cpa16(dst + B_BYTES, (const char*)Bl + go);
            }
        }
        asm volatile("cp.async.commit_group;");
    };

    float acc[4][4][4];
#pragma unroll
    for (int a = 0; a < 4; ++a)
#pragma unroll
        for (int b = 0; b < 4; ++b)
#pragma unroll
            for (int c = 0; c < 4; ++c) acc[a][b][c] = 0.f;

#pragma unroll
    for (int s = 0; s < NST - 1; ++s)
        if (s < nch) load_stage(s, s);

    const uint32_t a_row = (lane & 15);
    const uint32_t a_koff = ((lane >> 4) << 3);
    const uint32_t b_row = (lane & 7) + (((lane >> 4) & 1) << 3);
    const uint32_t b_koff = (((lane >> 3) & 1) << 3);

    for (int i = 0; i < nch; ++i) {
        if (i + NST - 1 <= nch) {
            asm volatile("cp.async.wait_group %0;" :: "n"(NST - 2));
        } else {
            asm volatile("cp.async.wait_group 0;");
        }
        __syncthreads();
        if (i + NST - 1 < nch) load_stage(i + NST - 1, (i + NST - 1) % NST);

        const uint32_t sb = smb + (i % NST) * STAGE_B;
#pragma unroll
        for (int ks = 0; ks < 2; ++ks) {
            const int k0 = ks * 16;
            uint32_t afh[4][4], afl[4][4];
#pragma unroll
            for (int mi = 0; mi < 4; ++mi) {
                const uint32_t addr =
                    sb + (wm * 64 + mi * 16 + a_row) * SROW + (k0 + a_koff) * 2;
                ldm4(afh[mi], addr);
                ldm4(afl[mi], addr + A_BYTES);
            }
            uint32_t bfh[2][4], bfl[2][4];
#pragma unroll
            for (int g = 0; g < 2; ++g) {
                const uint32_t addr =
                    sb + 2 * A_BYTES + (wn * 32 + g * 16 + b_row) * SROW + (k0 + b_koff) * 2;
                ldm4(bfh[g], addr);
                ldm4(bfl[g], addr + B_BYTES);
            }
#pragma unroll
            for (int mi = 0; mi < 4; ++mi)
#pragma unroll
                for (int ni = 0; ni < 4; ++ni) {
                    const int g = ni >> 1;
                    const int hf = (ni & 1) * 2;
                    mma_bf16(acc[mi][ni], afh[mi], &bfh[g][hf]);
                    mma_bf16(acc[mi][ni], afh[mi], &bfl[g][hf]);
                    mma_bf16(acc[mi][ni], afl[mi], &bfh[g][hf]);
                }
        }
    }

    // epilogue: QKV scatter; Q scaled 0.125; V transposed; all bf16 pairs
    const int er = lane >> 2;
    const int ec = (lane & 3) * 2;
#pragma unroll
    for (int mi = 0; mi < 4; ++mi)
#pragma unroll
        for (int ni = 0; ni < 4; ++ni) {
#pragma unroll
            for (int half = 0; half < 2; ++half) {
                const int row = bm + wm * 64 + mi * 16 + er + half * 8;
                const int col = bn + wn * 32 + ni * 8 + ec;
                float v0 = acc[mi][ni][half * 2 + 0] + bias[col];
                float v1 = acc[mi][ni][half * 2 + 1] + bias[col + 1];
                const int t = col >> 10;
                const int cc = col & 1023;
                const int b = row >> 10, s = row & 1023;
                const int h = cc >> 6, d = cc & 63;
                if (t == 0) { v0 *= 0.125f; v1 *= 0.125f; }
                __nv_bfloat16 h0, l0, h1, l1;
                split_bf16(v0, h0, l0);
                split_bf16(v1, h1, l1);
                if (t < 2) {
                    __nv_bfloat16* Dh = (__nv_bfloat16*)(t == 0 ? Cf : Cf2);
                    __nv_bfloat16* Dl = Dh + HALFBUF;
                    const size_t o = ((size_t)(b * NHEAD + h) * 1024 + s) * DHEAD + d;
                    *(__nv_bfloat162*)(Dh + o) = __nv_bfloat162{h0, h1};
                    *(__nv_bfloat162*)(Dl + o) = __nv_bfloat162{l0, l1};
                } else {
                    __nv_bfloat16* Dh = (__nv_bfloat16*)Cf3;
                    __nv_bfloat16* Dl = Dh + HALFBUF;
                    const size_t o0 = ((size_t)(b * NHEAD + h) * DHEAD + d) * 1024 + s;
                    Dh[o0] = h0;
                    Dl[o0] = l0;
                    Dh[o0 + 1024] = h1;
                    Dl[o0 + 1024] = l1;
                }
            }
        }
}

// ---------------- fp16 2-term HMMA GEMM (Wo/W1/W2), 512 thr, 128x256 ----------------
// C = A(fp16 single) @ (Bh+Bl)(fp16 pair)^T.  EPI: 1 relu->fp16 single, 2 +res->fp32
#define A2_BYTES 10240
#define B2_BYTES 20480
#define STAGE2 (A2_BYTES + 2 * B2_BYTES)  // 51200
#define SMEM_G2 (3 * STAGE2)              // 153600

template <int EPI>
__global__ void __launch_bounds__(512, 1)
hgemm2(const __half* __restrict__ A, const __half* __restrict__ Bh,
       const __half* __restrict__ Bl, const float* __restrict__ bias,
       const float* __restrict__ res, float* __restrict__ Cf,
       __half* __restrict__ Chalf, int M, int N, int K) {
    extern __shared__ char sm[];
    const uint32_t smb = smem_u32(sm);
    const int tid = threadIdx.x;
    const int wid = tid >> 5;
    const int lane = tid & 31;
    const int wm = wid & 1;
    const int wn = wid >> 1;
    const int bm = blockIdx.y * 128;
    const int bn = blockIdx.x * 256;
    const int nch = K / HBK;

    auto load_stage = [&](int chunk, int s) {
        const int k0 = chunk * HBK;
        const uint32_t base = smb + s * STAGE2;
#pragma unroll
        for (int it = 0; it < 5; ++it) {
            const int idx = tid + (it << 9);  // 0..2559
            if (idx < 512) {
                const int r = idx >> 2, c4 = idx & 3;
                cpa16(base + r * SROW + c4 * 16,
                      (const char*)A + ((size_t)(bm + r) * K + k0 + c4 * 8) * 2);
            } else {
                const int j = idx - 512;
                const int hl = j >> 10;
                const int jj = j & 1023;
                const int r = jj >> 2, c4 = jj & 3;
                cpa16(base + A2_BYTES + hl * B2_BYTES + r * SROW + c4 * 16,
                      (const char*)(hl ? Bl : Bh) + ((size_t)(bn + r) * K + k0 + c4 * 8) * 2);
            }
        }
        asm volatile("cp.async.commit_group;");
    };

    float acc[4][4][4];
#pragma unroll
    for (int a = 0; a < 4; ++a)
#pragma unroll
        for (int b = 0; b < 4; ++b)
#pragma unroll
            for (int c = 0; c < 4; ++c) acc[a][b][c] = 0.f;

#pragma unroll
    for (int s = 0; s < NST - 1; ++s)
        if (s < nch) load_stage(s, s);

    const uint32_t a_row = (lane & 15);
    const uint32_t a_koff = ((lane >> 4) << 3);
    const uint32_t b_row = (lane & 7) + (((lane >> 4) & 1) << 3);
    const uint32_t b_koff = (((lane >> 3) & 1) << 3);

    for (int i = 0; i < nch; ++i) {
        if (i + NST - 1 <= nch) {
            asm volatile("cp.async.wait_group %0;" :: "n"(NST - 2));
        } else {
            asm volatile("cp.async.wait_group 0;");
        }
        __syncthreads();
        if (i + NST - 1 < nch) load_stage(i + NST - 1, (i + NST - 1) % NST);

        const uint32_t sb = smb + (i % NST) * STAGE2;
#pragma unroll
        for (int ks = 0; ks < 2; ++ks) {
            const int k0 = ks * 16;
            uint32_t af[4][4];
#pragma unroll
            for (int mi = 0; mi < 4; ++mi) {
                const uint32_t addr =
                    sb + (wm * 64 + mi * 16 + a_row) * SROW + (k0 + a_koff) * 2;
                ldm4(af[mi], addr);
            }
            uint32_t bfh[2][4], bfl[2][4];
#pragma unroll
            for (int g = 0; g < 2; ++g) {
                const uint32_t addr =
                    sb + A2_BYTES + (wn * 32 + g * 16 + b_row) * SROW + (k0 + b_koff) * 2;
                ldm4(bfh[g], addr);
                ldm4(bfl[g], addr + B2_BYTES);
            }
#pragma unroll
            for (int mi = 0; mi < 4; ++mi)
#pragma unroll
                for (int ni = 0; ni < 4; ++ni) {
                    const int g = ni >> 1;
                    const int hf = (ni & 1) * 2;
                    mma_fp16(acc[mi][ni], af[mi], &bfh[g][hf]);
                    mma_fp16(acc[mi][ni], af[mi], &bfl[g][hf]);
                }
        }
    }

    // epilogue
    const int er = lane >> 2;
    const int ec = (lane & 3) * 2;
#pragma unroll
    for (int mi = 0; mi < 4; ++mi)
#pragma unroll
        for (int ni = 0; ni < 4; ++ni) {
#pragma unroll
            for (int half = 0; half < 2; ++half) {
                const int row = bm + wm * 64 + mi * 16 + er + half * 8;
                const int col = bn + wn * 32 + ni * 8 + ec;
                float v0 = acc[mi][ni][half * 2 + 0] + bias[col];
                float v1 = acc[mi][ni][half * 2 + 1] + bias[col + 1];
                const size_t o = (size_t)row * N + col;
                if (EPI == 1) {
                    v0 = fmaxf(v0, 0.f);
                    v1 = fmaxf(v1, 0.f);
                    *(__half2*)(Chalf + o) = __floats2half2_rn(v0, v1);
                } else {
                    const float2 rv = *(const float2*)(res + o);
                    float2 ov;
                    ov.x = v0 + rv.x;
                    ov.y = v1 + rv.y;
                    *(float2*)(Cf + o) = ov;
                }
            }
        }
}

// ---------------- split-bf16 HMMA flash attention -> fp16 single CTX ----------------
#define AST 144
#define AQ_B 18432
#define AKV_T 9216
#define AKV_STAGE 36864
#define ATT_SMEM (2 * AQ_B + 3 * AKV_STAGE)  // 147456

__global__ void __launch_bounds__(256, 1)
attn_k(const __nv_bfloat16* __restrict__ Qhp, const __nv_bfloat16* __restrict__ Khp,
       const __nv_bfloat16* __restrict__ Vhp, __half* __restrict__ CTX) {
    const __nv_bfloat16* Qlp = Qhp + HALFBUF;
    const __nv_bfloat16* Klp = Khp + HALFBUF;
    const __nv_bfloat16* Vlp = Vhp + HALFBUF;

    extern __shared__ char sm[];
    const uint32_t smb = smem_u32(sm);
    const uint32_t QS = smb;
    const uint32_t KST0 = smb + 2 * AQ_B;

    const int tid = threadIdx.x;
    const int wid = tid >> 5;
    const int lane = tid & 31;
    const int bh = blockIdx.y;
    const int q0 = blockIdx.x << 7;

    {
#pragma unroll
        for (int it = 0; it < 8; ++it) {
            const int idx = tid + (it << 8);
            const int hl = idx >> 10;
            const int rem = idx & 1023;
            const int r = rem >> 3;
            const int c = rem & 7;
            const uint32_t dst = QS + hl * AQ_B + r * AST + c * 16;
            const char* src = (const char*)(hl ? Qlp : Qhp) +
                              (size_t)((bh << 10) + q0 + r) * 128 + c * 16;
            cpa16(dst, src);
        }
    }

    auto load_kv = [&](int kt, int s) {
        const uint32_t base = KST0 + s * AKV_STAGE;
#pragma unroll
        for (int it = 0; it < 8; ++it) {
            const int idx = tid + (it << 8);
            const int tensor = idx >> 10;
            const int rem = idx & 1023;
            const int r = rem >> 4;
            const int c = (rem >> 1) & 7;
            const int hl = rem & 1;
            if (tensor == 0) {
                const uint32_t dst = base + hl * AKV_T + r * AST + c * 16;
                const char* src = (const char*)(hl ? Klp : Khp) +
                                  (size_t)((bh << 10) + (kt << 6) + r) * 128 + c * 16;
                cpa16(dst, src);
            } else {
                const uint32_t dst = base + 2 * AKV_T + hl * AKV_T + r * AST + c * 16;
                const char* src = (const char*)(hl ? Vlp : Vhp) +
                                  (((size_t)(bh * 64 + r) << 10) + (kt << 6)) * 2 + c * 16;
                cpa16(dst, src);
            }
        }
        asm volatile("cp.async.commit_group;");
    };

    load_kv(0, 0);
    load_kv(1, 1);

    float m0 = -1e30f, m1 = -1e30f, l0 = 0.f, l1 = 0.f;
    float oacc[8][4];
#pragma unroll
    for (int i = 0; i < 8; ++i)
#pragma unroll
        for (int j = 0; j < 4; ++j) oacc[i][j] = 0.f;

    const uint32_t a_row = (lane & 15);
    const uint32_t a_koff = ((lane >> 4) << 3);
    const uint32_t b_row = (lane & 7) + (((lane >> 4) & 1) << 3);
    const uint32_t b_koff = (((lane >> 3) & 1) << 3);

    for (int kt = 0; kt < 16; ++kt) {
        if (kt + 2 <= 16) {
            asm volatile("cp.async.wait_group 1;");
        } else {
            asm volatile("cp.async.wait_group 0;");
        }
        __syncthreads();
        if (kt + 2 < 16) load_kv(kt + 2, (kt + 2) % 3);

        const uint32_t st = KST0 + (kt % 3) * AKV_STAGE;

        // ---- S = Q K^T ----
        float sacc[8][4];
#pragma unroll
        for (int i = 0; i < 8; ++i)
#pragma unroll
            for (int j = 0; j < 4; ++j) sacc[i][j] = 0.f;
#pragma unroll
        for (int kc = 0; kc < 4; ++kc) {
            uint32_t afh[4], afl[4];
            const uint32_t aaddr = QS + (wid * 16 + a_row) * AST + (kc * 16 + a_koff) * 2;
            ldm4(afh, aaddr);
            ldm4(afl, aaddr + AQ_B);
            uint32_t bkh[4][4], bkl[4][4];
#pragma unroll
            for (int g = 0; g < 4; ++g) {
                const uint32_t baddr = st + (g * 16 + b_row) * AST + (kc * 16 + b_koff) * 2;
                ldm4(bkh[g], baddr);
                ldm4(bkl[g], baddr + AKV_T);
            }
#pragma unroll
            for (int ni = 0; ni < 8; ++ni)
                mma_bf16(sacc[ni], afh, &bkh[ni >> 1][(ni & 1) * 2]);
#pragma unroll
            for (int ni = 0; ni < 8; ++ni)
                mma_bf16(sacc[ni], afh, &bkl[ni >> 1][(ni & 1) * 2]);
#pragma unroll
            for (int ni = 0; ni < 8; ++ni)
                mma_bf16(sacc[ni], afl, &bkh[ni >> 1][(ni & 1) * 2]);
        }

        // ---- online softmax ----
        float rmax0 = -1e30f, rmax1 = -1e30f;
#pragma unroll
        for (int ni = 0; ni < 8; ++ni) {
            rmax0 = fmaxf(rmax0, fmaxf(sacc[ni][0], sacc[ni][1]));
            rmax1 = fmaxf(rmax1, fmaxf(sacc[ni][2], sacc[ni][3]));
        }
        rmax0 = fmaxf(rmax0, __shfl_xor_sync(0xffffffffu, rmax0, 1));
        rmax0 = fmaxf(rmax0, __shfl_xor_sync(0xffffffffu, rmax0, 2));
        rmax1 = fmaxf(rmax1, __shfl_xor_sync(0xffffffffu, rmax1, 1));
        rmax1 = fmaxf(rmax1, __shfl_xor_sync(0xffffffffu, rmax1, 2));
        const float mn0 = fmaxf(m0, rmax0);
        const float mn1 = fmaxf(m1, rmax1);
        const float cor0 = __expf(m0 - mn0);
        const float cor1 = __expf(m1 - mn1);
        float rs0 = 0.f, rs1 = 0.f;
#pragma unroll
        for (int ni = 0; ni < 8; ++ni) {
            sacc[ni][0] = __expf(sacc[ni][0] - mn0);
            sacc[ni][1] = __expf(sacc[ni][1] - mn0);
            sacc[ni][2] = __expf(sacc[ni][2] - mn1);
            sacc[ni][3] = __expf(sacc[ni][3] - mn1);
            rs0 += sacc[ni][0] + sacc[ni][1];
            rs1 += sacc[ni][2] + sacc[ni][3];
        }
        rs0 += __shfl_xor_sync(0xffffffffu, rs0, 1);
        rs0 += __shfl_xor_sync(0xffffffffu, rs0, 2);
        rs1 += __shfl_xor_sync(0xffffffffu, rs1, 1);
        rs1 += __shfl_xor_sync(0xffffffffu, rs1, 2);
        l0 = l0 * cor0 + rs0;
        l1 = l1 * cor1 + rs1;
        m0 = mn0;
        m1 = mn1;
#pragma unroll
        for (int ni = 0; ni < 8; ++ni) {
            oacc[ni][0] *= cor0;
            oacc[ni][1] *= cor0;
            oacc[ni][2] *= cor1;
            oacc[ni][3] *= cor1;
        }

        // ---- O += P V ----
#pragma unroll
        for (int j = 0; j < 4; ++j) {
            uint32_t pah[4], pal[4];
#pragma unroll
            for (int tt = 0; tt < 2; ++tt) {
                const float* sc = sacc[2 * j + tt];
#pragma unroll
                for (int q = 0; q < 2; ++q) {
                    const float v0 = sc[2 * q], v1 = sc[2 * q + 1];
                    __nv_bfloat16 h0, e0, h1, e1;
                    split_bf16(v0, h0, e0);
                    split_bf16(v1, h1, e1);
                    pah[2 * tt + q] = pack_bf2(h0, h1);
                    pal[2 * tt + q] = pack_bf2(e0, e1);
                }
            }
            uint32_t bvh[4][4], bvl[4][4];
#pragma unroll
            for (int g = 0; g < 4; ++g) {
                const uint32_t baddr =
                    st + 2 * AKV_T + (g * 16 + b_row) * AST + (j * 16 + b_koff) * 2;
                ldm4(bvh[g], baddr);
                ldm4(bvl[g], baddr + AKV_T);
            }
#pragma unroll
            for (int ni = 0; ni < 8; ++ni)
                mma_bf16(oacc[ni], pah, &bvh[ni >> 1][(ni & 1) * 2]);
#pragma unroll
            for (int ni = 0; ni < 8; ++ni)
                mma_bf16(oacc[ni], pah, &bvl[ni >> 1][(ni & 1) * 2]);
#pragma unroll
            for (int ni = 0; ni < 8; ++ni)
                mma_bf16(oacc[ni], pal, &bvh[ni >> 1][(ni & 1) * 2]);
        }
    }

    // ---- epilogue: O /= l, write CTX fp16 single [B, S, D] ----
    const float inv0 = 1.0f / l0;
    const float inv1 = 1.0f / l1;
    const int b = bh >> 4, h = bh & 15;
    const int row0 = q0 + wid * 16 + (lane >> 2);
    const int ec = (lane & 3) * 2;
#pragma unroll
    for (int ni = 0; ni < 8; ++ni) {
        const int col = h * 64 + ni * 8 + ec;
        {
            const size_t o = ((size_t)(b * 1024 + row0) * DM) + col;
            *(__half2*)(CTX + o) = __floats2half2_rn(oacc[ni][0] * inv0, oacc[ni][1] * inv0);
        }
        {
            const size_t o = ((size_t)(b * 1024 + row0 + 8) * DM) + col;
            *(__half2*)(CTX + o) = __floats2half2_rn(oacc[ni][2] * inv1, oacc[ni][3] * inv1);
        }
    }
}

// ---------------- launch ----------------
extern "C" void kernel_launch(void* const* d_in, const int* in_sizes, int n_in,
                              void* d_out, int out_size) {
    const float* src = (const float*)d_in[0];
    const float* Wq = (const float*)d_in[1];
    const float* bq = (const float*)d_in[2];
    const float* Wk = (const float*)d_in[3];
    const float* bk = (const float*)d_in[4];
    const float* Wv = (const float*)d_in[5];
    const float* bv = (const float*)d_in[6];
    const float* Wo = (const float*)d_in[7];
    const float* bo = (const float*)d_in[8];
    const float* W1 = (const float*)d_in[9];
    const float* b1 = (const float*)d_in[10];
    const float* W2 = (const float*)d_in[11];
    const float* b2 = (const float*)d_in[12];
    const float* g1 = (const float*)d_in[13];
    const float* be1 = (const float*)d_in[14];
    const float* g2 = (const float*)d_in[15];
    const float* be2 = (const float*)d_in[16];
    float* out = (float*)d_out;

#define SYM(p, s) cudaGetSymbolAddress((void**)&p, s)
    __nv_bfloat16 *Xh, *Xl, *Wqkvh, *Wqkvl;
    __half *Cx, *Y2, *Hx, *Woh, *Wol, *W1h, *W1l, *W2h, *W2l;
    float *Qb, *Kb, *Vb, *S2, *bqkv;
    SYM(Xh, g_Xh); SYM(Xl, g_Xl);
    SYM(Cx, g_Cx); SYM(Y2, g_Y2); SYM(Hx, g_Hx);
    SYM(Qb, g_Q); SYM(Kb, g_K); SYM(Vb, g_V); SYM(S2, g_S2); SYM(bqkv, g_bqkv);
    SYM(Wqkvh, g_Wqkvh); SYM(Wqkvl, g_Wqkvl);
    SYM(Woh, g_Woh); SYM(Wol, g_Wol);
    SYM(W1h, g_W1h); SYM(W1l, g_W1l); SYM(W2h, g_W2h); SYM(W2l, g_W2l);
#undef SYM

    cudaFuncSetAttribute(attn_k, cudaFuncAttributeMaxDynamicSharedMemorySize, ATT_SMEM);
    cudaFuncSetAttribute(hgemm_qkv, cudaFuncAttributeMaxDynamicSharedMemorySize, SMEM_G);
    cudaFuncSetAttribute(hgemm2<1>, cudaFuncAttributeMaxDynamicSharedMemorySize, SMEM_G2);
    cudaFuncSetAttribute(hgemm2<2>, cudaFuncAttributeMaxDynamicSharedMemorySize, SMEM_G2);

    dim3 cb(32, 8);
    // kernel 1: fused QKV weight conv + bias concat (bf16 pair)
    wconv3_k<<<dim3(DM / 32, DM / 32, 3), cb>>>(Wq, Wk, Wv, bq, bk, bv, Wqkvh, Wqkvl, bqkv);
    // kernel 2: LN1 -> bf16 pair
    ln_k<<<TOKENS, 256>>>(src, g1, be1, Xh, Xl);
    // kernel 3: Wo conv -> fp16 pair
    wconvh_k<<<dim3(DM / 32, DM / 32), cb>>>(Wo, Woh, Wol, DM, DM);

    // kernel 4: fused QKV GEMM (bf16 3-term, N=3072) — profiled control
    hgemm_qkv<<<dim3(12, 64), 512, SMEM_G>>>(
        Xh, Xl, Wqkvh, Wqkvl, bqkv, Qb, Kb, Vb, TOKENS, 3 * DM, DM);

    // kernel 5: HMMA flash attention -> CTX fp16 single
    attn_k<<<dim3(8, 128), 256, ATT_SMEM>>>(
        (const __nv_bfloat16*)Qb, (const __nv_bfloat16*)Kb, (const __nv_bfloat16*)Vb, Cx);

    // Wo (fp16 2-term) + residual(src) -> S2 fp32
    hgemm2<2><<<dim3(4, 64), 512, SMEM_G2>>>(
        Cx, Woh, Wol, bo, src, S2, nullptr, TOKENS, DM, DM);

    // LN2 -> fp16 single
    ln_h_k<<<TOKENS, 256>>>(S2, g2, be2, Y2);

    // W1 conv + W1 GEMM (fp16 2-term, relu) -> H fp16
    wconvh_k<<<dim3(DFF / 32, DM / 32), cb>>>(W1, W1h, W1l, DM, DFF);
    hgemm2<1><<<dim3(16, 64), 512, SMEM_G2>>>(
        Y2, W1h, W1l, b1, nullptr, nullptr, Hx, TOKENS, DFF, DM);

    // W2 conv + W2 GEMM (fp16 2-term) + residual(S2) -> out
    wconvh_k<<<dim3(DM / 32, DFF / 32), cb>>>(W2, W2h, W2l, DFF, DM);
    hgemm2<2><<<dim3(4, 64), 512, SMEM_G2>>>(
        Hx, W2h, W2l, b2, S2, out, nullptr, TOKENS, DM, DFF);
}

// round 14
// speedup vs baseline: 1.4950x; 1.2218x over previous
#include <cuda_runtime.h>
#include <cuda_bf16.h>
#include <cuda_fp16.h>
#include <cstdint>

#define TOKENS 8192
#define DM 1024
#define DFF 4096
#define NHEAD 16
#define DHEAD 64

// ---------------- scratch (device globals; no runtime alloc allowed) ----------------
__device__ __half g_X1[TOKENS * DM];                  // LN1 out (fp16 single)
__device__ __half g_Cx[TOKENS * DM];                  // ctx (fp16 single)
__device__ __half g_Y2[TOKENS * DM];                  // LN2 out (fp16 single)
__device__ __half g_Hx[(size_t)TOKENS * DFF];         // ffn hidden (fp16 single)
__device__ __half g_Qh[TOKENS * DM];                  // Q fp16 [BH,S,64], pre-scaled
__device__ __half g_Kh[TOKENS * DM];                  // K fp16 [BH,S,64]
__device__ __half g_Vt[TOKENS * DM];                  // V fp16 transposed [BH,64,S]
__device__ float g_S2[TOKENS * DM];
__device__ float g_bqkv[3 * DM];
__device__ __half g_Wqkvh[3 * DM * DM], g_Wqkvl[3 * DM * DM];  // fp16 pair
__device__ __half g_Woh[DM * DM], g_Wol[DM * DM];
__device__ __half g_W1h[(size_t)DM * DFF], g_W1l[(size_t)DM * DFF];
__device__ __half g_W2h[(size_t)DM * DFF], g_W2l[(size_t)DM * DFF];

// ---------------- PTX helpers ----------------
__device__ __forceinline__ uint32_t smem_u32(const void* p) {
    uint32_t a;
    asm("{ .reg .u64 t; cvta.to.shared.u64 t, %1; cvt.u32.u64 %0, t; }" : "=r"(a) : "l"(p));
    return a;
}
__device__ __forceinline__ void cpa16(uint32_t s, const void* g) {
    asm volatile("cp.async.cg.shared.global [%0], [%1], 16;" :: "r"(s), "l"(g));
}
__device__ __forceinline__ void ldm4(uint32_t* r, uint32_t addr) {
    asm volatile("ldmatrix.sync.aligned.m8n8.x4.shared.b16 {%0,%1,%2,%3}, [%4];"
                 : "=r"(r[0]), "=r"(r[1]), "=r"(r[2]), "=r"(r[3])
                 : "r"(addr));
}
__device__ __forceinline__ void mma_fp16(float* c, const uint32_t* a, const uint32_t* b) {
    asm volatile(
        "mma.sync.aligned.m16n8k16.row.col.f32.f16.f16.f32 "
        "{%0,%1,%2,%3}, {%4,%5,%6,%7}, {%8,%9}, {%0,%1,%2,%3};"
        : "+f"(c[0]), "+f"(c[1]), "+f"(c[2]), "+f"(c[3])
        : "r"(a[0]), "r"(a[1]), "r"(a[2]), "r"(a[3]), "r"(b[0]), "r"(b[1]));
}
__device__ __forceinline__ void split_h(float v, __half& h, __half& l) {
    h = __float2half_rn(v);
    l = __float2half_rn(v - __half2float(h));
}
__device__ __forceinline__ uint32_t packh2(float a, float b) {
    __half2 t = __floats2half2_rn(a, b);
    return *(uint32_t*)&t;
}

// ------- fused QKV weight transpose+split (fp16 pair) + bias concat -------
__global__ void __launch_bounds__(256) wconv3h_k(const float* __restrict__ Wq,
                                                 const float* __restrict__ Wk,
                                                 const float* __restrict__ Wv,
                                                 const float* __restrict__ bq,
                                                 const float* __restrict__ bk,
                                                 const float* __restrict__ bv,
                                                 __half* __restrict__ Th,
                                                 __half* __restrict__ Tl,
                                                 float* __restrict__ bqkv) {
    const int z = blockIdx.z;
    const float* W = (z == 0) ? Wq : (z == 1) ? Wk : Wv;
    const float* bi = (z == 0) ? bq : (z == 1) ? bk : bv;
    __half* Tz = Th + (size_t)z * DM * DM;
    __half* Tzl = Tl + (size_t)z * DM * DM;

    __shared__ float t[32][33];
    const int bx = blockIdx.x * 32;
    const int by = blockIdx.y * 32;
    const int x = threadIdx.x;
    const int y0 = threadIdx.y;
#pragma unroll
    for (int dy = 0; dy < 32; dy += 8)
        t[y0 + dy][x] = W[(size_t)(by + y0 + dy) * DM + bx + x];
    __syncthreads();
#pragma unroll
    for (int dy = 0; dy < 32; dy += 8) {
        const float v = t[x][y0 + dy];
        __half h, l;
        split_h(v, h, l);
        const size_t o = (size_t)(bx + y0 + dy) * DM + by + x;
        Tz[o] = h;
        Tzl[o] = l;
    }
    if (blockIdx.y == 0 && y0 == 0) bqkv[z * DM + bx + x] = bi[bx + x];
}

// ---------------- weight transpose + split to fp16 pair ----------------
__global__ void __launch_bounds__(256) wconvh_k(const float* __restrict__ W,
                                                __half* __restrict__ Th,
                                                __half* __restrict__ Tl,
                                                int K, int N) {
    __shared__ float t[32][33];
    const int bx = blockIdx.x * 32;
    const int by = blockIdx.y * 32;
    const int x = threadIdx.x;
    const int y0 = threadIdx.y;
#pragma unroll
    for (int dy = 0; dy < 32; dy += 8)
        t[y0 + dy][x] = W[(size_t)(by + y0 + dy) * N + bx + x];
    __syncthreads();
#pragma unroll
    for (int dy = 0; dy < 32; dy += 8) {
        const float v = t[x][y0 + dy];
        __half h, l;
        split_h(v, h, l);
        const size_t o = (size_t)(bx + y0 + dy) * K + by + x;
        Th[o] = h;
        Tl[o] = l;
    }
}

// ---------------- LayerNorm -> single fp16 ----------------
__global__ void __launch_bounds__(256) ln_h_k(const float* __restrict__ x,
                                              const float* __restrict__ g,
                                              const float* __restrict__ be,
                                              __half* __restrict__ y) {
    const int row = blockIdx.x;
    const int t = threadIdx.x;
    const size_t base = (size_t)row * DM;
    const float4 v = *(const float4*)(x + base + t * 4);
    float s = v.x + v.y + v.z + v.w;
    float q = v.x * v.x + v.y * v.y + v.z * v.z + v.w * v.w;
#pragma unroll
    for (int off = 16; off; off >>= 1) {
        s += __shfl_xor_sync(0xffffffffu, s, off);
        q += __shfl_xor_sync(0xffffffffu, q, off);
    }
    __shared__ float rs[8], rq[8];
    if ((t & 31) == 0) { rs[t >> 5] = s; rq[t >> 5] = q; }
    __syncthreads();
    s = 0.f; q = 0.f;
#pragma unroll
    for (int i = 0; i < 8; ++i) { s += rs[i]; q += rq[i]; }
    const float mu = s * (1.0f / DM);
    const float var = q * (1.0f / DM) - mu * mu;
    const float r = rsqrtf(var + 1e-5f);
    const float4 gv = *(const float4*)(g + t * 4);
    const float4 bv = *(const float4*)(be + t * 4);
    const float y0 = (v.x - mu) * r * gv.x + bv.x;
    const float y1 = (v.y - mu) * r * gv.y + bv.y;
    const float y2 = (v.z - mu) * r * gv.z + bv.z;
    const float y3 = (v.w - mu) * r * gv.w + bv.w;
    *(__half2*)(y + base + t * 4) = __floats2half2_rn(y0, y1);
    *(__half2*)(y + base + t * 4 + 2) = __floats2half2_rn(y2, y3);
}

// ---------------- fp16 2-term HMMA GEMM, 512 thr, tile 128x256 ----------------
// C = A(fp16 single) @ (Bh+Bl)(fp16 pair)^T.
// EPI: 1 relu->fp16, 2 +res->fp32, 3 QKV scatter fp16 (Q scaled, V transposed)
#define HBK 32
#define SROW 80
#define A2_BYTES 10240
#define B2_BYTES 20480
#define STAGE2 (A2_BYTES + 2 * B2_BYTES)  // 51200
#define NST 3
#define SMEM_G2 (NST * STAGE2)            // 153600

template <int EPI>
__global__ void __launch_bounds__(512, 1)
hgemm2(const __half* __restrict__ A, const __half* __restrict__ Bh,
       const __half* __restrict__ Bl, const float* __restrict__ bias,
       const float* __restrict__ res, float* __restrict__ Cf,
       __half* __restrict__ Ch1, __half* __restrict__ Ch2, __half* __restrict__ Ch3,
       int M, int N, int K) {
    extern __shared__ char sm[];
    const uint32_t smb = smem_u32(sm);
    const int tid = threadIdx.x;
    const int wid = tid >> 5;
    const int lane = tid & 31;
    const int wm = wid & 1;
    const int wn = wid >> 1;
    const int bm = blockIdx.y * 128;
    const int bn = blockIdx.x * 256;
    const int nch = K / HBK;

    auto load_stage = [&](int chunk, int s) {
        const int k0 = chunk * HBK;
        const uint32_t base = smb + s * STAGE2;
#pragma unroll
        for (int it = 0; it < 5; ++it) {
            const int idx = tid + (it << 9);  // 0..2559
            if (idx < 512) {
                const int r = idx >> 2, c4 = idx & 3;
                cpa16(base + r * SROW + c4 * 16,
                      (const char*)A + ((size_t)(bm + r) * K + k0 + c4 * 8) * 2);
            } else {
                const int j = idx - 512;
                const int hl = j >> 10;
                const int jj = j & 1023;
                const int r = jj >> 2, c4 = jj & 3;
                cpa16(base + A2_BYTES + hl * B2_BYTES + r * SROW + c4 * 16,
                      (const char*)(hl ? Bl : Bh) + ((size_t)(bn + r) * K + k0 + c4 * 8) * 2);
            }
        }
        asm volatile("cp.async.commit_group;");
    };

    float acc[4][4][4];
#pragma unroll
    for (int a = 0; a < 4; ++a)
#pragma unroll
        for (int b = 0; b < 4; ++b)
#pragma unroll
            for (int c = 0; c < 4; ++c) acc[a][b][c] = 0.f;

#pragma unroll
    for (int s = 0; s < NST - 1; ++s)
        if (s < nch) load_stage(s, s);

    const uint32_t a_row = (lane & 15);
    const uint32_t a_koff = ((lane >> 4) << 3);
    const uint32_t b_row = (lane & 7) + (((lane >> 4) & 1) << 3);
    const uint32_t b_koff = (((lane >> 3) & 1) << 3);

    for (int i = 0; i < nch; ++i) {
        if (i + NST - 1 <= nch) {
            asm volatile("cp.async.wait_group %0;" :: "n"(NST - 2));
        } else {
            asm volatile("cp.async.wait_group 0;");
        }
        __syncthreads();
        if (i + NST - 1 < nch) load_stage(i + NST - 1, (i + NST - 1) % NST);

        const uint32_t sb = smb + (i % NST) * STAGE2;
#pragma unroll
        for (int ks = 0; ks < 2; ++ks) {
            const int k0 = ks * 16;
            uint32_t af[4][4];
#pragma unroll
            for (int mi = 0; mi < 4; ++mi) {
                const uint32_t addr =
                    sb + (wm * 64 + mi * 16 + a_row) * SROW + (k0 + a_koff) * 2;
                ldm4(af[mi], addr);
            }
            uint32_t bfh[2][4], bfl[2][4];
#pragma unroll
            for (int g = 0; g < 2; ++g) {
                const uint32_t addr =
                    sb + A2_BYTES + (wn * 32 + g * 16 + b_row) * SROW + (k0 + b_koff) * 2;
                ldm4(bfh[g], addr);
                ldm4(bfl[g], addr + B2_BYTES);
            }
#pragma unroll
            for (int mi = 0; mi < 4; ++mi)
#pragma unroll
                for (int ni = 0; ni < 4; ++ni) {
                    const int g = ni >> 1;
                    const int hf = (ni & 1) * 2;
                    mma_fp16(acc[mi][ni], af[mi], &bfh[g][hf]);
                    mma_fp16(acc[mi][ni], af[mi], &bfl[g][hf]);
                }
        }
    }

    // epilogue
    const int er = lane >> 2;
    const int ec = (lane & 3) * 2;
#pragma unroll
    for (int mi = 0; mi < 4; ++mi)
#pragma unroll
        for (int ni = 0; ni < 4; ++ni) {
#pragma unroll
            for (int half = 0; half < 2; ++half) {
                const int row = bm + wm * 64 + mi * 16 + er + half * 8;
                const int col = bn + wn * 32 + ni * 8 + ec;
                float v0 = acc[mi][ni][half * 2 + 0] + bias[col];
                float v1 = acc[mi][ni][half * 2 + 1] + bias[col + 1];
                if (EPI == 1) {
                    v0 = fmaxf(v0, 0.f);
                    v1 = fmaxf(v1, 0.f);
                    const size_t o = (size_t)row * N + col;
                    *(__half2*)(Ch1 + o) = __floats2half2_rn(v0, v1);
                } else if (EPI == 2) {
                    const size_t o = (size_t)row * N + col;
                    const float2 rv = *(const float2*)(res + o);
                    float2 ov;
                    ov.x = v0 + rv.x;
                    ov.y = v1 + rv.y;
                    *(float2*)(Cf + o) = ov;
                } else {  // EPI == 3: QKV scatter fp16; Q scaled; V transposed
                    const int t = col >> 10;
                    const int cc = col & 1023;
                    const int b = row >> 10, s = row & 1023;
                    const int h = cc >> 6, d = cc & 63;
                    if (t == 0) { v0 *= 0.125f; v1 *= 0.125f; }
                    if (t < 2) {
                        __half* D = (t == 0) ? Ch1 : Ch2;
                        const size_t o = ((size_t)(b * NHEAD + h) * 1024 + s) * DHEAD + d;
                        *(__half2*)(D + o) = __floats2half2_rn(v0, v1);
                    } else {
                        const size_t o0 = ((size_t)(b * NHEAD + h) * DHEAD + d) * 1024 + s;
                        Ch3[o0] = __float2half_rn(v0);
                        Ch3[o0 + 1024] = __float2half_rn(v1);
                    }
                }
            }
        }
}

// ---------------- fp16 single-term HMMA flash attention ----------------
// Q [BH,S,64] fp16 (pre-scaled), K [BH,S,64] fp16, Vt [BH,64,S] fp16.
// CTA: 128 q rows, 8 warps, kv tiles of 64, 3-stage cp.async, 2 CTAs/SM.
#define AST 144          // 64 fp16 = 128 B + 16 pad
#define AQ_B 18432       // 128 * 144
#define AKV_T 9216       // 64 * 144
#define AKV_STAGE 18432  // K + V tiles
#define ATT_SMEM (AQ_B + 3 * AKV_STAGE)  // 73728

__global__ void __launch_bounds__(256, 2)
attn_k(const __half* __restrict__ Qp, const __half* __restrict__ Kp,
       const __half* __restrict__ Vp, __half* __restrict__ CTX) {
    extern __shared__ char sm[];
    const uint32_t smb = smem_u32(sm);
    const uint32_t QS = smb;
    const uint32_t KST0 = smb + AQ_B;

    const int tid = threadIdx.x;
    const int wid = tid >> 5;
    const int lane = tid & 31;
    const int bh = blockIdx.y;
    const int q0 = blockIdx.x << 7;

    // Q tile load (joins group of kv tile 0)
    {
#pragma unroll
        for (int it = 0; it < 4; ++it) {
            const int idx = tid + (it << 8);  // 0..1023
            const int r = idx >> 3;
            const int c = idx & 7;
            cpa16(QS + r * AST + c * 16,
                  (const char*)Qp + (size_t)((bh << 10) + q0 + r) * 128 + c * 16);
        }
    }

    auto load_kv = [&](int kt, int s) {
        const uint32_t base = KST0 + s * AKV_STAGE;
#pragma unroll
        for (int it = 0; it < 4; ++it) {
            const int idx = tid + (it << 8);  // 0..1023
            const int half_sel = idx >> 9;
            const int rem = idx & 511;
            const int r = rem >> 3;
            const int c = rem & 7;
            if (half_sel == 0) {
                cpa16(base + r * AST + c * 16,
                      (const char*)Kp + (size_t)((bh << 10) + (kt << 6) + r) * 128 + c * 16);
            } else {
                cpa16(base + AKV_T + r * AST + c * 16,
                      (const char*)Vp + (((size_t)(bh * 64 + r) << 10) + (kt << 6)) * 2 + c * 16);
            }
        }
        asm volatile("cp.async.commit_group;");
    };

    load_kv(0, 0);
    load_kv(1, 1);

    float m0 = -1e30f, m1 = -1e30f, l0 = 0.f, l1 = 0.f;
    float oacc[8][4];
#pragma unroll
    for (int i = 0; i < 8; ++i)
#pragma unroll
        for (int j = 0; j < 4; ++j) oacc[i][j] = 0.f;

    const uint32_t a_row = (lane & 15);
    const uint32_t a_koff = ((lane >> 4) << 3);
    const uint32_t b_row = (lane & 7) + (((lane >> 4) & 1) << 3);
    const uint32_t b_koff = (((lane >> 3) & 1) << 3);

    for (int kt = 0; kt < 16; ++kt) {
        if (kt + 2 <= 16) {
            asm volatile("cp.async.wait_group 1;");
        } else {
            asm volatile("cp.async.wait_group 0;");
        }
        __syncthreads();
        if (kt + 2 < 16) load_kv(kt + 2, (kt + 2) % 3);

        const uint32_t st = KST0 + (kt % 3) * AKV_STAGE;

        // ---- S = Q K^T (single term) ----
        float sacc[8][4];
#pragma unroll
        for (int i = 0; i < 8; ++i)
#pragma unroll
            for (int j = 0; j < 4; ++j) sacc[i][j] = 0.f;
#pragma unroll
        for (int kc = 0; kc < 4; ++kc) {
            uint32_t af[4];
            ldm4(af, QS + (wid * 16 + a_row) * AST + (kc * 16 + a_koff) * 2);
            uint32_t bk[4][4];
#pragma unroll
            for (int g = 0; g < 4; ++g)
                ldm4(bk[g], st + (g * 16 + b_row) * AST + (kc * 16 + b_koff) * 2);
#pragma unroll
            for (int ni = 0; ni < 8; ++ni)
                mma_fp16(sacc[ni], af, &bk[ni >> 1][(ni & 1) * 2]);
        }

        // ---- online softmax ----
        float rmax0 = -1e30f, rmax1 = -1e30f;
#pragma unroll
        for (int ni = 0; ni < 8; ++ni) {
            rmax0 = fmaxf(rmax0, fmaxf(sacc[ni][0], sacc[ni][1]));
            rmax1 = fmaxf(rmax1, fmaxf(sacc[ni][2], sacc[ni][3]));
        }
        rmax0 = fmaxf(rmax0, __shfl_xor_sync(0xffffffffu, rmax0, 1));
        rmax0 = fmaxf(rmax0, __shfl_xor_sync(0xffffffffu, rmax0, 2));
        rmax1 = fmaxf(rmax1, __shfl_xor_sync(0xffffffffu, rmax1, 1));
        rmax1 = fmaxf(rmax1, __shfl_xor_sync(0xffffffffu, rmax1, 2));
        const float mn0 = fmaxf(m0, rmax0);
        const float mn1 = fmaxf(m1, rmax1);
        const float cor0 = __expf(m0 - mn0);
        const float cor1 = __expf(m1 - mn1);
        float rs0 = 0.f, rs1 = 0.f;
#pragma unroll
        for (int ni = 0; ni < 8; ++ni) {
            sacc[ni][0] = __expf(sacc[ni][0] - mn0);
            sacc[ni][1] = __expf(sacc[ni][1] - mn0);
            sacc[ni][2] = __expf(sacc[ni][2] - mn1);
            sacc[ni][3] = __expf(sacc[ni][3] - mn1);
            rs0 += sacc[ni][0] + sacc[ni][1];
            rs1 += sacc[ni][2] + sacc[ni][3];
        }
        rs0 += __shfl_xor_sync(0xffffffffu, rs0, 1);
        rs0 += __shfl_xor_sync(0xffffffffu, rs0, 2);
        rs1 += __shfl_xor_sync(0xffffffffu, rs1, 1);
        rs1 += __shfl_xor_sync(0xffffffffu, rs1, 2);
        l0 = l0 * cor0 + rs0;
        l1 = l1 * cor1 + rs1;
        m0 = mn0;
        m1 = mn1;
#pragma unroll
        for (int ni = 0; ni < 8; ++ni) {
            oacc[ni][0] *= cor0;
            oacc[ni][1] *= cor0;
            oacc[ni][2] *= cor1;
            oacc[ni][3] *= cor1;
        }

        // ---- O += P V (single term) ----
#pragma unroll
        for (int j = 0; j < 4; ++j) {
            uint32_t pa[4];
#pragma unroll
            for (int tt = 0; tt < 2; ++tt) {
                const float* sc = sacc[2 * j + tt];
                pa[2 * tt + 0] = packh2(sc[0], sc[1]);
                pa[2 * tt + 1] = packh2(sc[2], sc[3]);
            }
            uint32_t bv[4][4];
#pragma unroll
            for (int g = 0; g < 4; ++g)
                ldm4(bv[g], st + AKV_T + (g * 16 + b_row) * AST + (j * 16 + b_koff) * 2);
#pragma unroll
            for (int ni = 0; ni < 8; ++ni)
                mma_fp16(oacc[ni], pa, &bv[ni >> 1][(ni & 1) * 2]);
        }
    }

    // ---- epilogue: O /= l, write CTX fp16 single [B, S, D] ----
    const float inv0 = 1.0f / l0;
    const float inv1 = 1.0f / l1;
    const int b = bh >> 4, h = bh & 15;
    const int row0 = q0 + wid * 16 + (lane >> 2);
    const int ec = (lane & 3) * 2;
#pragma unroll
    for (int ni = 0; ni < 8; ++ni) {
        const int col = h * 64 + ni * 8 + ec;
        {
            const size_t o = ((size_t)(b * 1024 + row0) * DM) + col;
            *(__half2*)(CTX + o) = __floats2half2_rn(oacc[ni][0] * inv0, oacc[ni][1] * inv0);
        }
        {
            const size_t o = ((size_t)(b * 1024 + row0 + 8) * DM) + col;
            *(__half2*)(CTX + o) = __floats2half2_rn(oacc[ni][2] * inv1, oacc[ni][3] * inv1);
        }
    }
}

// ---------------- launch ----------------
extern "C" void kernel_launch(void* const* d_in, const int* in_sizes, int n_in,
                              void* d_out, int out_size) {
    const float* src = (const float*)d_in[0];
    const float* Wq = (const float*)d_in[1];
    const float* bq = (const float*)d_in[2];
    const float* Wk = (const float*)d_in[3];
    const float* bk = (const float*)d_in[4];
    const float* Wv = (const float*)d_in[5];
    const float* bv = (const float*)d_in[6];
    const float* Wo = (const float*)d_in[7];
    const float* bo = (const float*)d_in[8];
    const float* W1 = (const float*)d_in[9];
    const float* b1 = (const float*)d_in[10];
    const float* W2 = (const float*)d_in[11];
    const float* b2 = (const float*)d_in[12];
    const float* g1 = (const float*)d_in[13];
    const float* be1 = (const float*)d_in[14];
    const float* g2 = (const float*)d_in[15];
    const float* be2 = (const float*)d_in[16];
    float* out = (float*)d_out;

#define SYM(p, s) cudaGetSymbolAddress((void**)&p, s)
    __half *X1, *Cx, *Y2, *Hx, *Qh, *Kh, *Vt;
    __half *Wqkvh, *Wqkvl, *Woh, *Wol, *W1h, *W1l, *W2h, *W2l;
    float *S2, *bqkv;
    SYM(X1, g_X1); SYM(Cx, g_Cx); SYM(Y2, g_Y2); SYM(Hx, g_Hx);
    SYM(Qh, g_Qh); SYM(Kh, g_Kh); SYM(Vt, g_Vt);
    SYM(S2, g_S2); SYM(bqkv, g_bqkv);
    SYM(Wqkvh, g_Wqkvh); SYM(Wqkvl, g_Wqkvl);
    SYM(Woh, g_Woh); SYM(Wol, g_Wol);
    SYM(W1h, g_W1h); SYM(W1l, g_W1l); SYM(W2h, g_W2h); SYM(W2l, g_W2l);
#undef SYM

    cudaFuncSetAttribute(attn_k, cudaFuncAttributeMaxDynamicSharedMemorySize, ATT_SMEM);
    cudaFuncSetAttribute(hgemm2<1>, cudaFuncAttributeMaxDynamicSharedMemorySize, SMEM_G2);
    cudaFuncSetAttribute(hgemm2<2>, cudaFuncAttributeMaxDynamicSharedMemorySize, SMEM_G2);
    cudaFuncSetAttribute(hgemm2<3>, cudaFuncAttributeMaxDynamicSharedMemorySize, SMEM_G2);

    dim3 cb(32, 8);
    // kernel 1: fused QKV weight conv (fp16 pair) + bias concat
    wconv3h_k<<<dim3(DM / 32, DM / 32, 3), cb>>>(Wq, Wk, Wv, bq, bk, bv, Wqkvh, Wqkvl, bqkv);
    // kernel 2: LN1 -> fp16 single
    ln_h_k<<<TOKENS, 256>>>(src, g1, be1, X1);
    // kernel 3: Wo conv -> fp16 pair
    wconvh_k<<<dim3(DM / 32, DM / 32), cb>>>(Wo, Woh, Wol, DM, DM);

    // kernel 4: fused QKV GEMM (fp16 2-term, N=3072) — profiled
    hgemm2<3><<<dim3(12, 64), 512, SMEM_G2>>>(
        X1, Wqkvh, Wqkvl, bqkv, nullptr, nullptr, Qh, Kh, Vt, TOKENS, 3 * DM, DM);

    // kernel 5: fp16 single-term flash attention -> CTX fp16
    attn_k<<<dim3(8, 128), 256, ATT_SMEM>>>(Qh, Kh, Vt, Cx);

    // Wo (fp16 2-term) + residual(src) -> S2 fp32
    hgemm2<2><<<dim3(4, 64), 512, SMEM_G2>>>(
        Cx, Woh, Wol, bo, src, S2, nullptr, nullptr, nullptr, TOKENS, DM, DM);

    // LN2 -> fp16 single
    ln_h_k<<<TOKENS, 256>>>(S2, g2, be2, Y2);

    // W1 conv + W1 GEMM (fp16 2-term, relu) -> H fp16
    wconvh_k<<<dim3(DFF / 32, DM / 32), cb>>>(W1, W1h, W1l, DM, DFF);
    hgemm2<1><<<dim3(16, 64), 512, SMEM_G2>>>(
        Y2, W1h, W1l, b1, nullptr, nullptr, Hx, nullptr, nullptr, TOKENS, DFF, DM);

    // W2 conv + W2 GEMM (fp16 2-term) + residual(S2) -> out
    wconvh_k<<<dim3(DM / 32, DFF / 32), cb>>>(W2, W2h, W2l, DFF, DM);
    hgemm2<2><<<dim3(4, 64), 512, SMEM_G2>>>(
        Hx, W2h, W2l, b2, S2, out, nullptr, nullptr, nullptr, TOKENS, DM, DFF);
}

// round 16
// speedup vs baseline: 2.3720x; 1.5866x over previous
#include <cuda_runtime.h>
#include <cuda_bf16.h>
#include <cuda_fp16.h>
#include <cstdint>

#define TOKENS 8192
#define DM 1024
#define DFF 4096
#define NHEAD 16
#define DHEAD 64

// ---------------- scratch (device globals; no runtime alloc allowed) ----------------
__device__ __half g_X1[TOKENS * DM];                  // LN1 out (fp16)
__device__ __half g_Cx[TOKENS * DM];                  // ctx (fp16)
__device__ __half g_Y2[TOKENS * DM];                  // LN2 out (fp16)
__device__ __half g_Hx[(size_t)TOKENS * DFF];         // ffn hidden (fp16)
__device__ __half g_Qh[TOKENS * DM];                  // Q fp16 [BH,S,64], pre-scaled
__device__ __half g_Kh[TOKENS * DM];                  // K fp16 [BH,S,64]
__device__ __half g_Vt[TOKENS * DM];                  // V fp16 transposed [BH,64,S]
__device__ float g_S2[TOKENS * DM];
__device__ float g_bqkv[3 * DM];
__device__ __half g_Wqkv[3 * DM * DM];                // fp16 single, transposed [N,K]
__device__ __half g_Wo[DM * DM];
__device__ __half g_W1[(size_t)DM * DFF];
__device__ __half g_W2[(size_t)DM * DFF];

// ---------------- PTX helpers ----------------
__device__ __forceinline__ uint32_t smem_u32(const void* p) {
    uint32_t a;
    asm("{ .reg .u64 t; cvta.to.shared.u64 t, %1; cvt.u32.u64 %0, t; }" : "=r"(a) : "l"(p));
    return a;
}
__device__ __forceinline__ void cpa16(uint32_t s, const void* g) {
    asm volatile("cp.async.cg.shared.global [%0], [%1], 16;" :: "r"(s), "l"(g));
}
__device__ __forceinline__ void ldm4(uint32_t* r, uint32_t addr) {
    asm volatile("ldmatrix.sync.aligned.m8n8.x4.shared.b16 {%0,%1,%2,%3}, [%4];"
                 : "=r"(r[0]), "=r"(r[1]), "=r"(r[2]), "=r"(r[3])
                 : "r"(addr));
}
__device__ __forceinline__ void mma_fp16(float* c, const uint32_t* a, const uint32_t* b) {
    asm volatile(
        "mma.sync.aligned.m16n8k16.row.col.f32.f16.f16.f32 "
        "{%0,%1,%2,%3}, {%4,%5,%6,%7}, {%8,%9}, {%0,%1,%2,%3};"
        : "+f"(c[0]), "+f"(c[1]), "+f"(c[2]), "+f"(c[3])
        : "r"(a[0]), "r"(a[1]), "r"(a[2]), "r"(a[3]), "r"(b[0]), "r"(b[1]));
}
__device__ __forceinline__ uint32_t packh2(float a, float b) {
    __half2 t = __floats2half2_rn(a, b);
    return *(uint32_t*)&t;
}

// ------- fused QKV weight transpose (fp16 single) + bias concat -------
__global__ void __launch_bounds__(256) wconv3h_k(const float* __restrict__ Wq,
                                                 const float* __restrict__ Wk,
                                                 const float* __restrict__ Wv,
                                                 const float* __restrict__ bq,
                                                 const float* __restrict__ bk,
                                                 const float* __restrict__ bv,
                                                 __half* __restrict__ T,
                                                 float* __restrict__ bqkv) {
    const int z = blockIdx.z;
    const float* W = (z == 0) ? Wq : (z == 1) ? Wk : Wv;
    const float* bi = (z == 0) ? bq : (z == 1) ? bk : bv;
    __half* Tz = T + (size_t)z * DM * DM;

    __shared__ float t[32][33];
    const int bx = blockIdx.x * 32;
    const int by = blockIdx.y * 32;
    const int x = threadIdx.x;
    const int y0 = threadIdx.y;
#pragma unroll
    for (int dy = 0; dy < 32; dy += 8)
        t[y0 + dy][x] = W[(size_t)(by + y0 + dy) * DM + bx + x];
    __syncthreads();
#pragma unroll
    for (int dy = 0; dy < 32; dy += 8)
        Tz[(size_t)(bx + y0 + dy) * DM + by + x] = __float2half_rn(t[x][y0 + dy]);
    if (blockIdx.y == 0 && y0 == 0) bqkv[z * DM + bx + x] = bi[bx + x];
}

// ---------------- weight transpose to fp16 single ----------------
__global__ void __launch_bounds__(256) wconvh_k(const float* __restrict__ W,
                                                __half* __restrict__ T,
                                                int K, int N) {
    __shared__ float t[32][33];
    const int bx = blockIdx.x * 32;
    const int by = blockIdx.y * 32;
    const int x = threadIdx.x;
    const int y0 = threadIdx.y;
#pragma unroll
    for (int dy = 0; dy < 32; dy += 8)
        t[y0 + dy][x] = W[(size_t)(by + y0 + dy) * N + bx + x];
    __syncthreads();
#pragma unroll
    for (int dy = 0; dy < 32; dy += 8)
        T[(size_t)(bx + y0 + dy) * K + by + x] = __float2half_rn(t[x][y0 + dy]);
}

// ---------------- LayerNorm -> single fp16 ----------------
__global__ void __launch_bounds__(256) ln_h_k(const float* __restrict__ x,
                                              const float* __restrict__ g,
                                              const float* __restrict__ be,
                                              __half* __restrict__ y) {
    const int row = blockIdx.x;
    const int t = threadIdx.x;
    const size_t base = (size_t)row * DM;
    const float4 v = *(const float4*)(x + base + t * 4);
    float s = v.x + v.y + v.z + v.w;
    float q = v.x * v.x + v.y * v.y + v.z * v.z + v.w * v.w;
#pragma unroll
    for (int off = 16; off; off >>= 1) {
        s += __shfl_xor_sync(0xffffffffu, s, off);
        q += __shfl_xor_sync(0xffffffffu, q, off);
    }
    __shared__ float rs[8], rq[8];
    if ((t & 31) == 0) { rs[t >> 5] = s; rq[t >> 5] = q; }
    __syncthreads();
    s = 0.f; q = 0.f;
#pragma unroll
    for (int i = 0; i < 8; ++i) { s += rs[i]; q += rq[i]; }
    const float mu = s * (1.0f / DM);
    const float var = q * (1.0f / DM) - mu * mu;
    const float r = rsqrtf(var + 1e-5f);
    const float4 gv = *(const float4*)(g + t * 4);
    const float4 bv = *(const float4*)(be + t * 4);
    const float y0 = (v.x - mu) * r * gv.x + bv.x;
    const float y1 = (v.y - mu) * r * gv.y + bv.y;
    const float y2 = (v.z - mu) * r * gv.z + bv.z;
    const float y3 = (v.w - mu) * r * gv.w + bv.w;
    *(__half2*)(y + base + t * 4) = __floats2half2_rn(y0, y1);
    *(__half2*)(y + base + t * 4 + 2) = __floats2half2_rn(y2, y3);
}

// ---------------- fp16 1-term HMMA GEMM, 512 thr, tile 128x256 ----------------
// C = A(fp16) @ B(fp16)^T.  5-stage cp.async.
// EPI: 1 relu->fp16, 2 +res->fp32, 3 QKV scatter fp16 (Q scaled, V transposed)
#define HBK 32
#define SROW 80
#define A1_BYTES 10240   // 128 * 80
#define B1_BYTES 20480   // 256 * 80
#define STAGE1 (A1_BYTES + B1_BYTES)  // 30720
#define NST 5
#define SMEM_G1 (NST * STAGE1)        // 153600

template <int EPI>
__global__ void __launch_bounds__(512, 1)
hgemm1(const __half* __restrict__ A, const __half* __restrict__ B,
       const float* __restrict__ bias, const float* __restrict__ res,
       float* __restrict__ Cf, __half* __restrict__ Ch1, __half* __restrict__ Ch2,
       __half* __restrict__ Ch3, int M, int N, int K) {
    extern __shared__ char sm[];
    const uint32_t smb = smem_u32(sm);
    const int tid = threadIdx.x;
    const int wid = tid >> 5;
    const int lane = tid & 31;
    const int wm = wid & 1;
    const int wn = wid >> 1;
    const int bm = blockIdx.y * 128;
    const int bn = blockIdx.x * 256;
    const int nch = K / HBK;

    auto load_stage = [&](int chunk, int s) {
        const int k0 = chunk * HBK;
        const uint32_t base = smb + s * STAGE1;
#pragma unroll
        for (int it = 0; it < 3; ++it) {
            const int idx = tid + (it << 9);  // 0..1535
            const int r = idx >> 2, c4 = idx & 3;
            if (r < 128) {
                cpa16(base + r * SROW + c4 * 16,
                      (const char*)A + ((size_t)(bm + r) * K + k0 + c4 * 8) * 2);
            } else {
                const int rb = r - 128;
                cpa16(base + A1_BYTES + rb * SROW + c4 * 16,
                      (const char*)B + ((size_t)(bn + rb) * K + k0 + c4 * 8) * 2);
            }
        }
        asm volatile("cp.async.commit_group;");
    };

    float acc[4][4][4];
#pragma unroll
    for (int a = 0; a < 4; ++a)
#pragma unroll
        for (int b = 0; b < 4; ++b)
#pragma unroll
            for (int c = 0; c < 4; ++c) acc[a][b][c] = 0.f;

#pragma unroll
    for (int s = 0; s < NST - 1; ++s)
        if (s < nch) load_stage(s, s);

    const uint32_t a_row = (lane & 15);
    const uint32_t a_koff = ((lane >> 4) << 3);
    const uint32_t b_row = (lane & 7) + (((lane >> 4) & 1) << 3);
    const uint32_t b_koff = (((lane >> 3) & 1) << 3);

    for (int i = 0; i < nch; ++i) {
        if (i + NST - 1 <= nch) {
            asm volatile("cp.async.wait_group %0;" :: "n"(NST - 2));
        } else {
            asm volatile("cp.async.wait_group 0;");
        }
        __syncthreads();
        if (i + NST - 1 < nch) load_stage(i + NST - 1, (i + NST - 1) % NST);

        const uint32_t sb = smb + (i % NST) * STAGE1;
#pragma unroll
        for (int ks = 0; ks < 2; ++ks) {
            const int k0 = ks * 16;
            uint32_t af[4][4];
#pragma unroll
            for (int mi = 0; mi < 4; ++mi)
                ldm4(af[mi], sb + (wm * 64 + mi * 16 + a_row) * SROW + (k0 + a_koff) * 2);
            uint32_t bf[2][4];
#pragma unroll
            for (int g = 0; g < 2; ++g)
                ldm4(bf[g],
                     sb + A1_BYTES + (wn * 32 + g * 16 + b_row) * SROW + (k0 + b_koff) * 2);
#pragma unroll
            for (int mi = 0; mi < 4; ++mi)
#pragma unroll
                for (int ni = 0; ni < 4; ++ni)
                    mma_fp16(acc[mi][ni], af[mi], &bf[ni >> 1][(ni & 1) * 2]);
        }
    }

    // epilogue
    const int er = lane >> 2;
    const int ec = (lane & 3) * 2;
#pragma unroll
    for (int mi = 0; mi < 4; ++mi)
#pragma unroll
        for (int ni = 0; ni < 4; ++ni) {
#pragma unroll
            for (int half = 0; half < 2; ++half) {
                const int row = bm + wm * 64 + mi * 16 + er + half * 8;
                const int col = bn + wn * 32 + ni * 8 + ec;
                float v0 = acc[mi][ni][half * 2 + 0] + bias[col];
                float v1 = acc[mi][ni][half * 2 + 1] + bias[col + 1];
                if (EPI == 1) {
                    v0 = fmaxf(v0, 0.f);
                    v1 = fmaxf(v1, 0.f);
                    const size_t o = (size_t)row * N + col;
                    *(__half2*)(Ch1 + o) = __floats2half2_rn(v0, v1);
                } else if (EPI == 2) {
                    const size_t o = (size_t)row * N + col;
                    const float2 rv = *(const float2*)(res + o);
                    float2 ov;
                    ov.x = v0 + rv.x;
                    ov.y = v1 + rv.y;
                    *(float2*)(Cf + o) = ov;
                } else {  // EPI == 3: QKV scatter fp16; Q scaled; V transposed
                    const int t = col >> 10;
                    const int cc = col & 1023;
                    const int b = row >> 10, s = row & 1023;
                    const int h = cc >> 6, d = cc & 63;
                    if (t == 0) { v0 *= 0.125f; v1 *= 0.125f; }
                    if (t < 2) {
                        __half* D = (t == 0) ? Ch1 : Ch2;
                        const size_t o = ((size_t)(b * NHEAD + h) * 1024 + s) * DHEAD + d;
                        *(__half2*)(D + o) = __floats2half2_rn(v0, v1);
                    } else {
                        const size_t o0 = ((size_t)(b * NHEAD + h) * DHEAD + d) * 1024 + s;
                        Ch3[o0] = __float2half_rn(v0);
                        Ch3[o0 + 1024] = __float2half_rn(v1);
                    }
                }
            }
        }
}

// ---------------- fp16 single-term HMMA flash attention ----------------
#define AST 144
#define AQ_B 18432
#define AKV_T 9216
#define AKV_STAGE 18432
#define ATT_SMEM (AQ_B + 3 * AKV_STAGE)  // 73728

__global__ void __launch_bounds__(256, 2)
attn_k(const __half* __restrict__ Qp, const __half* __restrict__ Kp,
       const __half* __restrict__ Vp, __half* __restrict__ CTX) {
    extern __shared__ char sm[];
    const uint32_t smb = smem_u32(sm);
    const uint32_t QS = smb;
    const uint32_t KST0 = smb + AQ_B;

    const int tid = threadIdx.x;
    const int wid = tid >> 5;
    const int lane = tid & 31;
    const int bh = blockIdx.y;
    const int q0 = blockIdx.x << 7;

    {
#pragma unroll
        for (int it = 0; it < 4; ++it) {
            const int idx = tid + (it << 8);
            const int r = idx >> 3;
            const int c = idx & 7;
            cpa16(QS + r * AST + c * 16,
                  (const char*)Qp + (size_t)((bh << 10) + q0 + r) * 128 + c * 16);
        }
    }

    auto load_kv = [&](int kt, int s) {
        const uint32_t base = KST0 + s * AKV_STAGE;
#pragma unroll
        for (int it = 0; it < 4; ++it) {
            const int idx = tid + (it << 8);
            const int half_sel = idx >> 9;
            const int rem = idx & 511;
            const int r = rem >> 3;
            const int c = rem & 7;
            if (half_sel == 0) {
                cpa16(base + r * AST + c * 16,
                      (const char*)Kp + (size_t)((bh << 10) + (kt << 6) + r) * 128 + c * 16);
            } else {
                cpa16(base + AKV_T + r * AST + c * 16,
                      (const char*)Vp + (((size_t)(bh * 64 + r) << 10) + (kt << 6)) * 2 + c * 16);
            }
        }
        asm volatile("cp.async.commit_group;");
    };

    load_kv(0, 0);
    load_kv(1, 1);

    float m0 = -1e30f, m1 = -1e30f, l0 = 0.f, l1 = 0.f;
    float oacc[8][4];
#pragma unroll
    for (int i = 0; i < 8; ++i)
#pragma unroll
        for (int j = 0; j < 4; ++j) oacc[i][j] = 0.f;

    const uint32_t a_row = (lane & 15);
    const uint32_t a_koff = ((lane >> 4) << 3);
    const uint32_t b_row = (lane & 7) + (((lane >> 4) & 1) << 3);
    const uint32_t b_koff = (((lane >> 3) & 1) << 3);

    for (int kt = 0; kt < 16; ++kt) {
        if (kt + 2 <= 16) {
            asm volatile("cp.async.wait_group 1;");
        } else {
            asm volatile("cp.async.wait_group 0;");
        }
        __syncthreads();
        if (kt + 2 < 16) load_kv(kt + 2, (kt + 2) % 3);

        const uint32_t st = KST0 + (kt % 3) * AKV_STAGE;

        // ---- S = Q K^T ----
        float sacc[8][4];
#pragma unroll
        for (int i = 0; i < 8; ++i)
#pragma unroll
            for (int j = 0; j < 4; ++j) sacc[i][j] = 0.f;
#pragma unroll
        for (int kc = 0; kc < 4; ++kc) {
            uint32_t af[4];
            ldm4(af, QS + (wid * 16 + a_row) * AST + (kc * 16 + a_koff) * 2);
            uint32_t bk[4][4];
#pragma unroll
            for (int g = 0; g < 4; ++g)
                ldm4(bk[g], st + (g * 16 + b_row) * AST + (kc * 16 + b_koff) * 2);
#pragma unroll
            for (int ni = 0; ni < 8; ++ni)
                mma_fp16(sacc[ni], af, &bk[ni >> 1][(ni & 1) * 2]);
        }

        // ---- online softmax ----
        float rmax0 = -1e30f, rmax1 = -1e30f;
#pragma unroll
        for (int ni = 0; ni < 8; ++ni) {
            rmax0 = fmaxf(rmax0, fmaxf(sacc[ni][0], sacc[ni][1]));
            rmax1 = fmaxf(rmax1, fmaxf(sacc[ni][2], sacc[ni][3]));
        }
        rmax0 = fmaxf(rmax0, __shfl_xor_sync(0xffffffffu, rmax0, 1));
        rmax0 = fmaxf(rmax0, __shfl_xor_sync(0xffffffffu, rmax0, 2));
        rmax1 = fmaxf(rmax1, __shfl_xor_sync(0xffffffffu, rmax1, 1));
        rmax1 = fmaxf(rmax1, __shfl_xor_sync(0xffffffffu, rmax1, 2));
        const float mn0 = fmaxf(m0, rmax0);
        const float mn1 = fmaxf(m1, rmax1);
        const float cor0 = __expf(m0 - mn0);
        const float cor1 = __expf(m1 - mn1);
        float rs0 = 0.f, rs1 = 0.f;
#pragma unroll
        for (int ni = 0; ni < 8; ++ni) {
            sacc[ni][0] = __expf(sacc[ni][0] - mn0);
            sacc[ni][1] = __expf(sacc[ni][1] - mn0);
            sacc[ni][2] = __expf(sacc[ni][2] - mn1);
            sacc[ni][3] = __expf(sacc[ni][3] - mn1);
            rs0 += sacc[ni][0] + sacc[ni][1];
            rs1 += sacc[ni][2] + sacc[ni][3];
        }
        rs0 += __shfl_xor_sync(0xffffffffu, rs0, 1);
        rs0 += __shfl_xor_sync(0xffffffffu, rs0, 2);
        rs1 += __shfl_xor_sync(0xffffffffu, rs1, 1);
        rs1 += __shfl_xor_sync(0xffffffffu, rs1, 2);
        l0 = l0 * cor0 + rs0;
        l1 = l1 * cor1 + rs1;
        m0 = mn0;
        m1 = mn1;
#pragma unroll
        for (int ni = 0; ni < 8; ++ni) {
            oacc[ni][0] *= cor0;
            oacc[ni][1] *= cor0;
            oacc[ni][2] *= cor1;
            oacc[ni][3] *= cor1;
        }

        // ---- O += P V ----
#pragma unroll
        for (int j = 0; j < 4; ++j) {
            uint32_t pa[4];
#pragma unroll
            for (int tt = 0; tt < 2; ++tt) {
                const float* sc = sacc[2 * j + tt];
                pa[2 * tt + 0] = packh2(sc[0], sc[1]);
                pa[2 * tt + 1] = packh2(sc[2], sc[3]);
            }
            uint32_t bv[4][4];
#pragma unroll
            for (int g = 0; g < 4; ++g)
                ldm4(bv[g], st + AKV_T + (g * 16 + b_row) * AST + (j * 16 + b_koff) * 2);
#pragma unroll
            for (int ni = 0; ni < 8; ++ni)
                mma_fp16(oacc[ni], pa, &bv[ni >> 1][(ni & 1) * 2]);
        }
    }

    // ---- epilogue ----
    const float inv0 = 1.0f / l0;
    const float inv1 = 1.0f / l1;
    const int b = bh >> 4, h = bh & 15;
    const int row0 = q0 + wid * 16 + (lane >> 2);
    const int ec = (lane & 3) * 2;
#pragma unroll
    for (int ni = 0; ni < 8; ++ni) {
        const int col = h * 64 + ni * 8 + ec;
        {
            const size_t o = ((size_t)(b * 1024 + row0) * DM) + col;
            *(__half2*)(CTX + o) = __floats2half2_rn(oacc[ni][0] * inv0, oacc[ni][1] * inv0);
        }
        {
            const size_t o = ((size_t)(b * 1024 + row0 + 8) * DM) + col;
            *(__half2*)(CTX + o) = __floats2half2_rn(oacc[ni][2] * inv1, oacc[ni][3] * inv1);
        }
    }
}

// ---------------- launch ----------------
extern "C" void kernel_launch(void* const* d_in, const int* in_sizes, int n_in,
                              void* d_out, int out_size) {
    const float* src = (const float*)d_in[0];
    const float* Wq = (const float*)d_in[1];
    const float* bq = (const float*)d_in[2];
    const float* Wk = (const float*)d_in[3];
    const float* bk = (const float*)d_in[4];
    const float* Wv = (const float*)d_in[5];
    const float* bv = (const float*)d_in[6];
    const float* Wo = (const float*)d_in[7];
    const float* bo = (const float*)d_in[8];
    const float* W1 = (const float*)d_in[9];
    const float* b1 = (const float*)d_in[10];
    const float* W2 = (const float*)d_in[11];
    const float* b2 = (const float*)d_in[12];
    const float* g1 = (const float*)d_in[13];
    const float* be1 = (const float*)d_in[14];
    const float* g2 = (const float*)d_in[15];
    const float* be2 = (const float*)d_in[16];
    float* out = (float*)d_out;

#define SYM(p, s) cudaGetSymbolAddress((void**)&p, s)
    __half *X1, *Cx, *Y2, *Hx, *Qh, *Kh, *Vt;
    __half *Wqkv, *Wot, *W1t, *W2t;
    float *S2, *bqkv;
    SYM(X1, g_X1); SYM(Cx, g_Cx); SYM(Y2, g_Y2); SYM(Hx, g_Hx);
    SYM(Qh, g_Qh); SYM(Kh, g_Kh); SYM(Vt, g_Vt);
    SYM(S2, g_S2); SYM(bqkv, g_bqkv);
    SYM(Wqkv, g_Wqkv); SYM(Wot, g_Wo); SYM(W1t, g_W1); SYM(W2t, g_W2);
#undef SYM

    cudaFuncSetAttribute(attn_k, cudaFuncAttributeMaxDynamicSharedMemorySize, ATT_SMEM);
    cudaFuncSetAttribute(hgemm1<1>, cudaFuncAttributeMaxDynamicSharedMemorySize, SMEM_G1);
    cudaFuncSetAttribute(hgemm1<2>, cudaFuncAttributeMaxDynamicSharedMemorySize, SMEM_G1);
    cudaFuncSetAttribute(hgemm1<3>, cudaFuncAttributeMaxDynamicSharedMemorySize, SMEM_G1);

    dim3 cb(32, 8);
    // kernel 1: fused QKV weight conv + bias concat
    wconv3h_k<<<dim3(DM / 32, DM / 32, 3), cb>>>(Wq, Wk, Wv, bq, bk, bv, Wqkv, bqkv);
    // kernel 2: LN1 -> fp16
    ln_h_k<<<TOKENS, 256>>>(src, g1, be1, X1);
    // kernel 3: Wo conv
    wconvh_k<<<dim3(DM / 32, DM / 32), cb>>>(Wo, Wot, DM, DM);

    // kernel 4: fused QKV GEMM (fp16 1-term, N=3072) — profiled
    hgemm1<3><<<dim3(12, 64), 512, SMEM_G1>>>(
        X1, Wqkv, bqkv, nullptr, nullptr, Qh, Kh, Vt, TOKENS, 3 * DM, DM);

    // kernel 5: fp16 flash attention -> CTX fp16
    attn_k<<<dim3(8, 128), 256, ATT_SMEM>>>(Qh, Kh, Vt, Cx);

    // Wo + residual(src) -> S2 fp32
    hgemm1<2><<<dim3(4, 64), 512, SMEM_G1>>>(
        Cx, Wot, bo, src, S2, nullptr, nullptr, nullptr, TOKENS, DM, DM);

    // LN2 -> fp16
    ln_h_k<<<TOKENS, 256>>>(S2, g2, be2, Y2);

    // W1 conv + W1 GEMM (relu) -> H fp16
    wconvh_k<<<dim3(DFF / 32, DM / 32), cb>>>(W1, W1t, DM, DFF);
    hgemm1<1><<<dim3(16, 64), 512, SMEM_G1>>>(
        Y2, W1t, b1, nullptr, nullptr, Hx, nullptr, nullptr, TOKENS, DFF, DM);

    // W2 conv + W2 GEMM + residual(S2) -> out
    wconvh_k<<<dim3(DM / 32, DFF / 32), cb>>>(W2, W2t, DFF, DM);
    hgemm1<2><<<dim3(4, 64), 512, SMEM_G1>>>(
        Hx, W2t, b2, S2, out, nullptr, nullptr, nullptr, TOKENS, DM, DFF);
}

// round 17
// speedup vs baseline: 2.6310x; 1.1092x over previous
#include <cuda_runtime.h>
#include <cuda_bf16.h>
#include <cuda_fp16.h>
#include <cstdint>

#define TOKENS 8192
#define DM 1024
#define DFF 4096
#define NHEAD 16
#define DHEAD 64

// ---------------- scratch (device globals; no runtime alloc allowed) ----------------
__device__ __half g_X1[TOKENS * DM];                  // LN1 out (fp16)
__device__ __half g_Cx[TOKENS * DM];                  // ctx (fp16)
__device__ __half g_Y2[TOKENS * DM];                  // LN2 out (fp16)
__device__ __half g_Hx[(size_t)TOKENS * DFF];         // ffn hidden (fp16)
__device__ __half g_Qh[TOKENS * DM];                  // Q fp16 [BH,S,64], pre-scaled
__device__ __half g_Kh[TOKENS * DM];                  // K fp16 [BH,S,64]
__device__ __half g_Vt[TOKENS * DM];                  // V fp16 transposed [BH,64,S]
__device__ float g_S2[TOKENS * DM];
__device__ float g_bqkv[3 * DM];
__device__ __half g_Wqkv[3 * DM * DM];                // fp16 single, transposed [N,K]
__device__ __half g_Wo[DM * DM];
__device__ __half g_W1[(size_t)DM * DFF];
__device__ __half g_W2[(size_t)DM * DFF];

// ---------------- PTX helpers ----------------
__device__ __forceinline__ uint32_t smem_u32(const void* p) {
    uint32_t a;
    asm("{ .reg .u64 t; cvta.to.shared.u64 t, %1; cvt.u32.u64 %0, t; }" : "=r"(a) : "l"(p));
    return a;
}
__device__ __forceinline__ void cpa16(uint32_t s, const void* g) {
    asm volatile("cp.async.cg.shared.global [%0], [%1], 16;" :: "r"(s), "l"(g));
}
__device__ __forceinline__ void ldm4(uint32_t* r, uint32_t addr) {
    asm volatile("ldmatrix.sync.aligned.m8n8.x4.shared.b16 {%0,%1,%2,%3}, [%4];"
                 : "=r"(r[0]), "=r"(r[1]), "=r"(r[2]), "=r"(r[3])
                 : "r"(addr));
}
__device__ __forceinline__ void mma_fp16(float* c, const uint32_t* a, const uint32_t* b) {
    asm volatile(
        "mma.sync.aligned.m16n8k16.row.col.f32.f16.f16.f32 "
        "{%0,%1,%2,%3}, {%4,%5,%6,%7}, {%8,%9}, {%0,%1,%2,%3};"
        : "+f"(c[0]), "+f"(c[1]), "+f"(c[2]), "+f"(c[3])
        : "r"(a[0]), "r"(a[1]), "r"(a[2]), "r"(a[3]), "r"(b[0]), "r"(b[1]));
}
__device__ __forceinline__ uint32_t packh2(float a, float b) {
    __half2 t = __floats2half2_rn(a, b);
    return *(uint32_t*)&t;
}

// ------- fused QKV weight transpose (fp16 single) + bias concat -------
__global__ void __launch_bounds__(256) wconv3h_k(const float* __restrict__ Wq,
                                                 const float* __restrict__ Wk,
                                                 const float* __restrict__ Wv,
                                                 const float* __restrict__ bq,
                                                 const float* __restrict__ bk,
                                                 const float* __restrict__ bv,
                                                 __half* __restrict__ T,
                                                 float* __restrict__ bqkv) {
    const int z = blockIdx.z;
    const float* W = (z == 0) ? Wq : (z == 1) ? Wk : Wv;
    const float* bi = (z == 0) ? bq : (z == 1) ? bk : bv;
    __half* Tz = T + (size_t)z * DM * DM;

    __shared__ float t[32][33];
    const int bx = blockIdx.x * 32;
    const int by = blockIdx.y * 32;
    const int x = threadIdx.x;
    const int y0 = threadIdx.y;
#pragma unroll
    for (int dy = 0; dy < 32; dy += 8)
        t[y0 + dy][x] = W[(size_t)(by + y0 + dy) * DM + bx + x];
    __syncthreads();
#pragma unroll
    for (int dy = 0; dy < 32; dy += 8)
        Tz[(size_t)(bx + y0 + dy) * DM + by + x] = __float2half_rn(t[x][y0 + dy]);
    if (blockIdx.y == 0 && y0 == 0) bqkv[z * DM + bx + x] = bi[bx + x];
}

// ---------------- weight transpose to fp16 single ----------------
__global__ void __launch_bounds__(256) wconvh_k(const float* __restrict__ W,
                                                __half* __restrict__ T,
                                                int K, int N) {
    __shared__ float t[32][33];
    const int bx = blockIdx.x * 32;
    const int by = blockIdx.y * 32;
    const int x = threadIdx.x;
    const int y0 = threadIdx.y;
#pragma unroll
    for (int dy = 0; dy < 32; dy += 8)
        t[y0 + dy][x] = W[(size_t)(by + y0 + dy) * N + bx + x];
    __syncthreads();
#pragma unroll
    for (int dy = 0; dy < 32; dy += 8)
        T[(size_t)(bx + y0 + dy) * K + by + x] = __float2half_rn(t[x][y0 + dy]);
}

// ---------------- LayerNorm -> single fp16 ----------------
__global__ void __launch_bounds__(256) ln_h_k(const float* __restrict__ x,
                                              const float* __restrict__ g,
                                              const float* __restrict__ be,
                                              __half* __restrict__ y) {
    const int row = blockIdx.x;
    const int t = threadIdx.x;
    const size_t base = (size_t)row * DM;
    const float4 v = *(const float4*)(x + base + t * 4);
    float s = v.x + v.y + v.z + v.w;
    float q = v.x * v.x + v.y * v.y + v.z * v.z + v.w * v.w;
#pragma unroll
    for (int off = 16; off; off >>= 1) {
        s += __shfl_xor_sync(0xffffffffu, s, off);
        q += __shfl_xor_sync(0xffffffffu, q, off);
    }
    __shared__ float rs[8], rq[8];
    if ((t & 31) == 0) { rs[t >> 5] = s; rq[t >> 5] = q; }
    __syncthreads();
    s = 0.f; q = 0.f;
#pragma unroll
    for (int i = 0; i < 8; ++i) { s += rs[i]; q += rq[i]; }
    const float mu = s * (1.0f / DM);
    const float var = q * (1.0f / DM) - mu * mu;
    const float r = rsqrtf(var + 1e-5f);
    const float4 gv = *(const float4*)(g + t * 4);
    const float4 bv = *(const float4*)(be + t * 4);
    const float y0 = (v.x - mu) * r * gv.x + bv.x;
    const float y1 = (v.y - mu) * r * gv.y + bv.y;
    const float y2 = (v.z - mu) * r * gv.z + bv.z;
    const float y3 = (v.w - mu) * r * gv.w + bv.w;
    *(__half2*)(y + base + t * 4) = __floats2half2_rn(y0, y1);
    *(__half2*)(y + base + t * 4 + 2) = __floats2half2_rn(y2, y3);
}

// ---------------- fp16 1-term HMMA GEMM, BK=64, 512 thr, tile 128x256 ----------------
// C = A(fp16) @ B(fp16)^T.  3-stage cp.async, 16 barriers per K=1024.
// EPI: 1 relu->fp16, 2 +res->fp32, 3 QKV scatter fp16 (Q scaled, V transposed)
#define HBK 64
#define SR1 144          // 64 fp16 = 128 B + 16 pad
#define A1_BYTES 18432   // 128 * 144
#define B1_BYTES 36864   // 256 * 144
#define STAGE1 (A1_BYTES + B1_BYTES)  // 55296
#define NST 3
#define SMEM_G1 (NST * STAGE1)        // 165888

template <int EPI>
__global__ void __launch_bounds__(512, 1)
hgemm1(const __half* __restrict__ A, const __half* __restrict__ B,
       const float* __restrict__ bias, const float* __restrict__ res,
       float* __restrict__ Cf, __half* __restrict__ Ch1, __half* __restrict__ Ch2,
       __half* __restrict__ Ch3, int M, int N, int K) {
    extern __shared__ char sm[];
    const uint32_t smb = smem_u32(sm);
    const int tid = threadIdx.x;
    const int wid = tid >> 5;
    const int lane = tid & 31;
    const int wm = wid & 1;
    const int wn = wid >> 1;
    const int bm = blockIdx.y * 128;
    const int bn = blockIdx.x * 256;
    const int nch = K / HBK;

    auto load_stage = [&](int chunk, int s) {
        const int k0 = chunk * HBK;
        const uint32_t base = smb + s * STAGE1;
#pragma unroll
        for (int it = 0; it < 6; ++it) {
            const int idx = tid + (it << 9);  // 0..3071
            const int r = idx >> 3, c = idx & 7;  // 8x16B chunks per 128B row
            if (r < 128) {
                cpa16(base + r * SR1 + c * 16,
                      (const char*)A + ((size_t)(bm + r) * K + k0) * 2 + c * 16);
            } else {
                const int rb = r - 128;
                cpa16(base + A1_BYTES + rb * SR1 + c * 16,
                      (const char*)B + ((size_t)(bn + rb) * K + k0) * 2 + c * 16);
            }
        }
        asm volatile("cp.async.commit_group;");
    };

    float acc[4][4][4];
#pragma unroll
    for (int a = 0; a < 4; ++a)
#pragma unroll
        for (int b = 0; b < 4; ++b)
#pragma unroll
            for (int c = 0; c < 4; ++c) acc[a][b][c] = 0.f;

#pragma unroll
    for (int s = 0; s < NST - 1; ++s)
        if (s < nch) load_stage(s, s);

    const uint32_t a_row = (lane & 15);
    const uint32_t a_koff = ((lane >> 4) << 3);
    const uint32_t b_row = (lane & 7) + (((lane >> 4) & 1) << 3);
    const uint32_t b_koff = (((lane >> 3) & 1) << 3);

    for (int i = 0; i < nch; ++i) {
        if (i + NST - 1 <= nch) {
            asm volatile("cp.async.wait_group %0;" :: "n"(NST - 2));
        } else {
            asm volatile("cp.async.wait_group 0;");
        }
        __syncthreads();
        if (i + NST - 1 < nch) load_stage(i + NST - 1, (i + NST - 1) % NST);

        const uint32_t sb = smb + (i % NST) * STAGE1;
#pragma unroll
        for (int ks = 0; ks < 4; ++ks) {
            const int k0 = ks * 16;
            uint32_t af[4][4];
#pragma unroll
            for (int mi = 0; mi < 4; ++mi)
                ldm4(af[mi], sb + (wm * 64 + mi * 16 + a_row) * SR1 + (k0 + a_koff) * 2);
            uint32_t bf[2][4];
#pragma unroll
            for (int g = 0; g < 2; ++g)
                ldm4(bf[g],
                     sb + A1_BYTES + (wn * 32 + g * 16 + b_row) * SR1 + (k0 + b_koff) * 2);
#pragma unroll
            for (int mi = 0; mi < 4; ++mi)
#pragma unroll
                for (int ni = 0; ni < 4; ++ni)
                    mma_fp16(acc[mi][ni], af[mi], &bf[ni >> 1][(ni & 1) * 2]);
        }
    }

    // epilogue
    const int er = lane >> 2;
    const int ec = (lane & 3) * 2;
#pragma unroll
    for (int mi = 0; mi < 4; ++mi)
#pragma unroll
        for (int ni = 0; ni < 4; ++ni) {
#pragma unroll
            for (int half = 0; half < 2; ++half) {
                const int row = bm + wm * 64 + mi * 16 + er + half * 8;
                const int col = bn + wn * 32 + ni * 8 + ec;
                float v0 = acc[mi][ni][half * 2 + 0] + bias[col];
                float v1 = acc[mi][ni][half * 2 + 1] + bias[col + 1];
                if (EPI == 1) {
                    v0 = fmaxf(v0, 0.f);
                    v1 = fmaxf(v1, 0.f);
                    const size_t o = (size_t)row * N + col;
                    *(__half2*)(Ch1 + o) = __floats2half2_rn(v0, v1);
                } else if (EPI == 2) {
                    const size_t o = (size_t)row * N + col;
                    const float2 rv = *(const float2*)(res + o);
                    float2 ov;
                    ov.x = v0 + rv.x;
                    ov.y = v1 + rv.y;
                    *(float2*)(Cf + o) = ov;
                } else {  // EPI == 3: QKV scatter fp16; Q scaled; V transposed
                    const int t = col >> 10;
                    const int cc = col & 1023;
                    const int b = row >> 10, s = row & 1023;
                    const int h = cc >> 6, d = cc & 63;
                    if (t == 0) { v0 *= 0.125f; v1 *= 0.125f; }
                    if (t < 2) {
                        __half* D = (t == 0) ? Ch1 : Ch2;
                        const size_t o = ((size_t)(b * NHEAD + h) * 1024 + s) * DHEAD + d;
                        *(__half2*)(D + o) = __floats2half2_rn(v0, v1);
                    } else {
                        const size_t o0 = ((size_t)(b * NHEAD + h) * DHEAD + d) * 1024 + s;
                        Ch3[o0] = __float2half_rn(v0);
                        Ch3[o0 + 1024] = __float2half_rn(v1);
                    }
                }
            }
        }
}

// ---------------- fp16 single-term HMMA flash attention ----------------
#define AST 144
#define AQ_B 18432
#define AKV_T 9216
#define AKV_STAGE 18432
#define ATT_SMEM (AQ_B + 3 * AKV_STAGE)  // 73728

__global__ void __launch_bounds__(256, 2)
attn_k(const __half* __restrict__ Qp, const __half* __restrict__ Kp,
       const __half* __restrict__ Vp, __half* __restrict__ CTX) {
    extern __shared__ char sm[];
    const uint32_t smb = smem_u32(sm);
    const uint32_t QS = smb;
    const uint32_t KST0 = smb + AQ_B;

    const int tid = threadIdx.x;
    const int wid = tid >> 5;
    const int lane = tid & 31;
    const int bh = blockIdx.y;
    const int q0 = blockIdx.x << 7;

    {
#pragma unroll
        for (int it = 0; it < 4; ++it) {
            const int idx = tid + (it << 8);
            const int r = idx >> 3;
            const int c = idx & 7;
            cpa16(QS + r * AST + c * 16,
                  (const char*)Qp + (size_t)((bh << 10) + q0 + r) * 128 + c * 16);
        }
    }

    auto load_kv = [&](int kt, int s) {
        const uint32_t base = KST0 + s * AKV_STAGE;
#pragma unroll
        for (int it = 0; it < 4; ++it) {
            const int idx = tid + (it << 8);
            const int half_sel = idx >> 9;
            const int rem = idx & 511;
            const int r = rem >> 3;
            const int c = rem & 7;
            if (half_sel == 0) {
                cpa16(base + r * AST + c * 16,
                      (const char*)Kp + (size_t)((bh << 10) + (kt << 6) + r) * 128 + c * 16);
            } else {
                cpa16(base + AKV_T + r * AST + c * 16,
                      (const char*)Vp + (((size_t)(bh * 64 + r) << 10) + (kt << 6)) * 2 + c * 16);
            }
        }
        asm volatile("cp.async.commit_group;");
    };

    load_kv(0, 0);
    load_kv(1, 1);

    float m0 = -1e30f, m1 = -1e30f, l0 = 0.f, l1 = 0.f;
    float oacc[8][4];
#pragma unroll
    for (int i = 0; i < 8; ++i)
#pragma unroll
        for (int j = 0; j < 4; ++j) oacc[i][j] = 0.f;

    const uint32_t a_row = (lane & 15);
    const uint32_t a_koff = ((lane >> 4) << 3);
    const uint32_t b_row = (lane & 7) + (((lane >> 4) & 1) << 3);
    const uint32_t b_koff = (((lane >> 3) & 1) << 3);

    for (int kt = 0; kt < 16; ++kt) {
        if (kt + 2 <= 16) {
            asm volatile("cp.async.wait_group 1;");
        } else {
            asm volatile("cp.async.wait_group 0;");
        }
        __syncthreads();
        if (kt + 2 < 16) load_kv(kt + 2, (kt + 2) % 3);

        const uint32_t st = KST0 + (kt % 3) * AKV_STAGE;

        // ---- S = Q K^T ----
        float sacc[8][4];
#pragma unroll
        for (int i = 0; i < 8; ++i)
#pragma unroll
            for (int j = 0; j < 4; ++j) sacc[i][j] = 0.f;
#pragma unroll
        for (int kc = 0; kc < 4; ++kc) {
            uint32_t af[4];
            ldm4(af, QS + (wid * 16 + a_row) * AST + (kc * 16 + a_koff) * 2);
            uint32_t bk[4][4];
#pragma unroll
            for (int g = 0; g < 4; ++g)
                ldm4(bk[g], st + (g * 16 + b_row) * AST + (kc * 16 + b_koff) * 2);
#pragma unroll
            for (int ni = 0; ni < 8; ++ni)
                mma_fp16(sacc[ni], af, &bk[ni >> 1][(ni & 1) * 2]);
        }

        // ---- online softmax ----
        float rmax0 = -1e30f, rmax1 = -1e30f;
#pragma unroll
        for (int ni = 0; ni < 8; ++ni) {
            rmax0 = fmaxf(rmax0, fmaxf(sacc[ni][0], sacc[ni][1]));
            rmax1 = fmaxf(rmax1, fmaxf(sacc[ni][2], sacc[ni][3]));
        }
        rmax0 = fmaxf(rmax0, __shfl_xor_sync(0xffffffffu, rmax0, 1));
        rmax0 = fmaxf(rmax0, __shfl_xor_sync(0xffffffffu, rmax0, 2));
        rmax1 = fmaxf(rmax1, __shfl_xor_sync(0xffffffffu, rmax1, 1));
        rmax1 = fmaxf(rmax1, __shfl_xor_sync(0xffffffffu, rmax1, 2));
        const float mn0 = fmaxf(m0, rmax0);
        const float mn1 = fmaxf(m1, rmax1);
        const float cor0 = __expf(m0 - mn0);
        const float cor1 = __expf(m1 - mn1);
        float rs0 = 0.f, rs1 = 0.f;
#pragma unroll
        for (int ni = 0; ni < 8; ++ni) {
            sacc[ni][0] = __expf(sacc[ni][0] - mn0);
            sacc[ni][1] = __expf(sacc[ni][1] - mn0);
            sacc[ni][2] = __expf(sacc[ni][2] - mn1);
            sacc[ni][3] = __expf(sacc[ni][3] - mn1);
            rs0 += sacc[ni][0] + sacc[ni][1];
            rs1 += sacc[ni][2] + sacc[ni][3];
        }
        rs0 += __shfl_xor_sync(0xffffffffu, rs0, 1);
        rs0 += __shfl_xor_sync(0xffffffffu, rs0, 2);
        rs1 += __shfl_xor_sync(0xffffffffu, rs1, 1);
        rs1 += __shfl_xor_sync(0xffffffffu, rs1, 2);
        l0 = l0 * cor0 + rs0;
        l1 = l1 * cor1 + rs1;
        m0 = mn0;
        m1 = mn1;
#pragma unroll
        for (int ni = 0; ni < 8; ++ni) {
            oacc[ni][0] *= cor0;
            oacc[ni][1] *= cor0;
            oacc[ni][2] *= cor1;
            oacc[ni][3] *= cor1;
        }

        // ---- O += P V ----
#pragma unroll
        for (int j = 0; j < 4; ++j) {
            uint32_t pa[4];
#pragma unroll
            for (int tt = 0; tt < 2; ++tt) {
                const float* sc = sacc[2 * j + tt];
                pa[2 * tt + 0] = packh2(sc[0], sc[1]);
                pa[2 * tt + 1] = packh2(sc[2], sc[3]);
            }
            uint32_t bv[4][4];
#pragma unroll
            for (int g = 0; g < 4; ++g)
                ldm4(bv[g], st + AKV_T + (g * 16 + b_row) * AST + (j * 16 + b_koff) * 2);
#pragma unroll
            for (int ni = 0; ni < 8; ++ni)
                mma_fp16(oacc[ni], pa, &bv[ni >> 1][(ni & 1) * 2]);
        }
    }

    // ---- epilogue ----
    const float inv0 = 1.0f / l0;
    const float inv1 = 1.0f / l1;
    const int b = bh >> 4, h = bh & 15;
    const int row0 = q0 + wid * 16 + (lane >> 2);
    const int ec = (lane & 3) * 2;
#pragma unroll
    for (int ni = 0; ni < 8; ++ni) {
        const int col = h * 64 + ni * 8 + ec;
        {
            const size_t o = ((size_t)(b * 1024 + row0) * DM) + col;
            *(__half2*)(CTX + o) = __floats2half2_rn(oacc[ni][0] * inv0, oacc[ni][1] * inv0);
        }
        {
            const size_t o = ((size_t)(b * 1024 + row0 + 8) * DM) + col;
            *(__half2*)(CTX + o) = __floats2half2_rn(oacc[ni][2] * inv1, oacc[ni][3] * inv1);
        }
    }
}

// ---------------- launch ----------------
extern "C" void kernel_launch(void* const* d_in, const int* in_sizes, int n_in,
                              void* d_out, int out_size) {
    const float* src = (const float*)d_in[0];
    const float* Wq = (const float*)d_in[1];
    const float* bq = (const float*)d_in[2];
    const float* Wk = (const float*)d_in[3];
    const float* bk = (const float*)d_in[4];
    const float* Wv = (const float*)d_in[5];
    const float* bv = (const float*)d_in[6];
    const float* Wo = (const float*)d_in[7];
    const float* bo = (const float*)d_in[8];
    const float* W1 = (const float*)d_in[9];
    const float* b1 = (const float*)d_in[10];
    const float* W2 = (const float*)d_in[11];
    const float* b2 = (const float*)d_in[12];
    const float* g1 = (const float*)d_in[13];
    const float* be1 = (const float*)d_in[14];
    const float* g2 = (const float*)d_in[15];
    const float* be2 = (const float*)d_in[16];
    float* out = (float*)d_out;

#define SYM(p, s) cudaGetSymbolAddress((void**)&p, s)
    __half *X1, *Cx, *Y2, *Hx, *Qh, *Kh, *Vt;
    __half *Wqkv, *Wot, *W1t, *W2t;
    float *S2, *bqkv;
    SYM(X1, g_X1); SYM(Cx, g_Cx); SYM(Y2, g_Y2); SYM(Hx, g_Hx);
    SYM(Qh, g_Qh); SYM(Kh, g_Kh); SYM(Vt, g_Vt);
    SYM(S2, g_S2); SYM(bqkv, g_bqkv);
    SYM(Wqkv, g_Wqkv); SYM(Wot, g_Wo); SYM(W1t, g_W1); SYM(W2t, g_W2);
#undef SYM

    cudaFuncSetAttribute(attn_k, cudaFuncAttributeMaxDynamicSharedMemorySize, ATT_SMEM);
    cudaFuncSetAttribute(hgemm1<1>, cudaFuncAttributeMaxDynamicSharedMemorySize, SMEM_G1);
    cudaFuncSetAttribute(hgemm1<2>, cudaFuncAttributeMaxDynamicSharedMemorySize, SMEM_G1);
    cudaFuncSetAttribute(hgemm1<3>, cudaFuncAttributeMaxDynamicSharedMemorySize, SMEM_G1);

    dim3 cb(32, 8);
    // kernel 1: fused QKV weight conv + bias concat
    wconv3h_k<<<dim3(DM / 32, DM / 32, 3), cb>>>(Wq, Wk, Wv, bq, bk, bv, Wqkv, bqkv);
    // kernel 2: LN1 -> fp16
    ln_h_k<<<TOKENS, 256>>>(src, g1, be1, X1);
    // kernel 3: Wo conv
    wconvh_k<<<dim3(DM / 32, DM / 32), cb>>>(Wo, Wot, DM, DM);

    // kernel 4: fused QKV GEMM (fp16 1-term, BK=64, N=3072) — profiled
    hgemm1<3><<<dim3(12, 64), 512, SMEM_G1>>>(
        X1, Wqkv, bqkv, nullptr, nullptr, Qh, Kh, Vt, TOKENS, 3 * DM, DM);

    // kernel 5: fp16 flash attention -> CTX fp16
    attn_k<<<dim3(8, 128), 256, ATT_SMEM>>>(Qh, Kh, Vt, Cx);

    // Wo + residual(src) -> S2 fp32
    hgemm1<2><<<dim3(4, 64), 512, SMEM_G1>>>(
        Cx, Wot, bo, src, S2, nullptr, nullptr, nullptr, TOKENS, DM, DM);

    // LN2 -> fp16
    ln_h_k<<<TOKENS, 256>>>(S2, g2, be2, Y2);

    // W1 conv + W1 GEMM (relu) -> H fp16
    wconvh_k<<<dim3(DFF / 32, DM / 32), cb>>>(W1, W1t, DM, DFF);
    hgemm1<1><<<dim3(16, 64), 512, SMEM_G1>>>(
        Y2, W1t, b1, nullptr, nullptr, Hx, nullptr, nullptr, TOKENS, DFF, DM);

    // W2 conv + W2 GEMM + residual(S2) -> out
    wconvh_k<<<dim3(DM / 32, DFF / 32), cb>>>(W2, W2t, DFF, DM);
    hgemm1<2><<<dim3(4, 64), 512, SMEM_G1>>>(
        Hx, W2t, b2, S2, out, nullptr, nullptr, nullptr, TOKENS, DM, DFF);
}